// round 2
// baseline (speedup 1.0000x reference)
#include <cuda_runtime.h>
#include <cuda_bf16.h>
#include <math.h>

// ---------------- problem constants ----------------
#define S_LEN   1024
#define D_MODEL 5120
#define H_HEADS 128
#define Q_LORA  1536
#define KV_LORA 512
#define ROPE_D  64
#define NOPE_D  128
#define VDIM    128
#define Q_HEAD  192          // NOPE + ROPE
#define LATENT  576          // KV_LORA + ROPE
#define QBN     24576        // H * Q_HEAD
#define OUTW    16384        // H * VDIM

// ---------------- scratch (device globals; no allocation) ----------------
__device__ __align__(16) float g_qa   [S_LEN * Q_LORA];          // 6.3 MB
__device__ __align__(16) float g_q    [S_LEN * QBN];             // 100 MB
__device__ __align__(16) float g_kv   [S_LEN * LATENT];          // 2.4 MB
__device__ __align__(16) float g_kfull[S_LEN * LATENT];          // 2.4 MB
__device__ __align__(16) float g_qfull[(long)H_HEADS * S_LEN * LATENT];   // 302 MB
__device__ __align__(16) float g_veff [(long)H_HEADS * S_LEN * VDIM];     // 67 MB
__device__ __align__(16) float g_scores[(long)H_HEADS * S_LEN * S_LEN];   // 537 MB
__device__ __align__(16) float g_bigout[S_LEN * OUTW];           // 67 MB

// ---------------- generic 128x128x8 SGEMM (NN), strided-batched ----------------
__global__ void __launch_bounds__(256) gemm_nn_k(
    const float* __restrict__ A, const float* __restrict__ B, float* __restrict__ C,
    int M, int N, int K, int lda, int ldb, int ldc,
    long sA, long sB, long sC, float alpha)
{
    A += (long)blockIdx.z * sA;
    B += (long)blockIdx.z * sB;
    C += (long)blockIdx.z * sC;

    __shared__ __align__(16) float As[8][128];
    __shared__ __align__(16) float Bs[8][128];

    const int tid = threadIdx.x;
    const int tx = tid & 15;
    const int ty = tid >> 4;
    const int m0 = blockIdx.y * 128;
    const int n0 = blockIdx.x * 128;

    const int a_r = tid >> 1;
    const int a_k = (tid & 1) * 4;
    const int b_k = tid >> 5;
    const int b_n = (tid & 31) * 4;

    const float* Aptr = A + (long)(m0 + a_r) * lda + a_k;
    const float* Bptr = B + (long)b_k * ldb + n0 + b_n;
    const bool bvalid = (n0 + b_n) < N;

    float acc[8][8];
#pragma unroll
    for (int i = 0; i < 8; i++)
#pragma unroll
        for (int j = 0; j < 8; j++) acc[i][j] = 0.f;

    for (int k0 = 0; k0 < K; k0 += 8) {
        float4 av = *(const float4*)Aptr;
        As[a_k + 0][a_r] = av.x;
        As[a_k + 1][a_r] = av.y;
        As[a_k + 2][a_r] = av.z;
        As[a_k + 3][a_r] = av.w;
        float4 bv = bvalid ? *(const float4*)Bptr : make_float4(0.f, 0.f, 0.f, 0.f);
        *(float4*)&Bs[b_k][b_n] = bv;
        __syncthreads();
#pragma unroll
        for (int kk = 0; kk < 8; kk++) {
            float4 a0 = *(const float4*)&As[kk][ty * 4];
            float4 a1 = *(const float4*)&As[kk][64 + ty * 4];
            float4 b0 = *(const float4*)&Bs[kk][tx * 4];
            float4 b1 = *(const float4*)&Bs[kk][64 + tx * 4];
            float ar[8] = {a0.x, a0.y, a0.z, a0.w, a1.x, a1.y, a1.z, a1.w};
            float br[8] = {b0.x, b0.y, b0.z, b0.w, b1.x, b1.y, b1.z, b1.w};
#pragma unroll
            for (int i = 0; i < 8; i++)
#pragma unroll
                for (int j = 0; j < 8; j++)
                    acc[i][j] += ar[i] * br[j];
        }
        __syncthreads();
        Aptr += 8;
        Bptr += (long)8 * ldb;
    }

#pragma unroll
    for (int i = 0; i < 8; i++) {
        int m = m0 + ((i < 4) ? (ty * 4 + i) : (64 + ty * 4 + i - 4));
#pragma unroll
        for (int jj = 0; jj < 2; jj++) {
            int n = n0 + ((jj == 0) ? (tx * 4) : (64 + tx * 4));
            if (n < N) {
                float4 v;
                v.x = alpha * acc[i][jj * 4 + 0];
                v.y = alpha * acc[i][jj * 4 + 1];
                v.z = alpha * acc[i][jj * 4 + 2];
                v.w = alpha * acc[i][jj * 4 + 3];
                *(float4*)&C[(long)m * ldc + n] = v;
            }
        }
    }
}

// ---------------- generic 128x128x8 SGEMM (NT): C = A * B^T ----------------
__global__ void __launch_bounds__(256) gemm_nt_k(
    const float* __restrict__ A, const float* __restrict__ B, float* __restrict__ C,
    int M, int N, int K, int lda, int ldb, int ldc,
    long sA, long sB, long sC, float alpha)
{
    A += (long)blockIdx.z * sA;
    B += (long)blockIdx.z * sB;
    C += (long)blockIdx.z * sC;

    __shared__ __align__(16) float As[8][128];
    __shared__ __align__(16) float Bs[8][128];

    const int tid = threadIdx.x;
    const int tx = tid & 15;
    const int ty = tid >> 4;
    const int m0 = blockIdx.y * 128;
    const int n0 = blockIdx.x * 128;

    const int a_r = tid >> 1;
    const int a_k = (tid & 1) * 4;
    const int b_r = tid >> 1;           // n-index
    const int b_kk = (tid & 1) * 4;

    const float* Aptr = A + (long)(m0 + a_r) * lda + a_k;
    const float* Bptr = B + (long)(n0 + b_r) * ldb + b_kk;
    const bool bvalid = (n0 + b_r) < N;

    float acc[8][8];
#pragma unroll
    for (int i = 0; i < 8; i++)
#pragma unroll
        for (int j = 0; j < 8; j++) acc[i][j] = 0.f;

    for (int k0 = 0; k0 < K; k0 += 8) {
        float4 av = *(const float4*)Aptr;
        As[a_k + 0][a_r] = av.x;
        As[a_k + 1][a_r] = av.y;
        As[a_k + 2][a_r] = av.z;
        As[a_k + 3][a_r] = av.w;
        float4 bv = bvalid ? *(const float4*)Bptr : make_float4(0.f, 0.f, 0.f, 0.f);
        Bs[b_kk + 0][b_r] = bv.x;
        Bs[b_kk + 1][b_r] = bv.y;
        Bs[b_kk + 2][b_r] = bv.z;
        Bs[b_kk + 3][b_r] = bv.w;
        __syncthreads();
#pragma unroll
        for (int kk = 0; kk < 8; kk++) {
            float4 a0 = *(const float4*)&As[kk][ty * 4];
            float4 a1 = *(const float4*)&As[kk][64 + ty * 4];
            float4 b0 = *(const float4*)&Bs[kk][tx * 4];
            float4 b1 = *(const float4*)&Bs[kk][64 + tx * 4];
            float ar[8] = {a0.x, a0.y, a0.z, a0.w, a1.x, a1.y, a1.z, a1.w};
            float br[8] = {b0.x, b0.y, b0.z, b0.w, b1.x, b1.y, b1.z, b1.w};
#pragma unroll
            for (int i = 0; i < 8; i++)
#pragma unroll
                for (int j = 0; j < 8; j++)
                    acc[i][j] += ar[i] * br[j];
        }
        __syncthreads();
        Aptr += 8;
        Bptr += 8;
    }

#pragma unroll
    for (int i = 0; i < 8; i++) {
        int m = m0 + ((i < 4) ? (ty * 4 + i) : (64 + ty * 4 + i - 4));
#pragma unroll
        for (int jj = 0; jj < 2; jj++) {
            int n = n0 + ((jj == 0) ? (tx * 4) : (64 + tx * 4));
            if (n < N) {
                float4 v;
                v.x = alpha * acc[i][jj * 4 + 0];
                v.y = alpha * acc[i][jj * 4 + 1];
                v.z = alpha * acc[i][jj * 4 + 2];
                v.w = alpha * acc[i][jj * 4 + 3];
                *(float4*)&C[(long)m * ldc + n] = v;
            }
        }
    }
}

// ---------------- in-place row rmsnorm ----------------
__global__ void rmsnorm_rows_k(float* x, const float* __restrict__ w, int W)
{
    int row = blockIdx.x;
    float* p = x + (long)row * W;
    __shared__ float red[256];
    int tid = threadIdx.x;
    float ss = 0.f;
    for (int i = tid; i < W; i += 256) { float v = p[i]; ss += v * v; }
    red[tid] = ss; __syncthreads();
    for (int st = 128; st > 0; st >>= 1) {
        if (tid < st) red[tid] += red[tid + st];
        __syncthreads();
    }
    float r = rsqrtf(red[0] / (float)W + 1e-6f);
    for (int i = tid; i < W; i += 256) p[i] = p[i] * r * w[i];
}

// ---------------- k_full: rmsnorm(latent) || rope(k_pe) ----------------
__global__ void build_kfull_k(const float* __restrict__ kv, const float* __restrict__ lnw,
                              const float* __restrict__ cosb, const float* __restrict__ sinb,
                              float* __restrict__ kfull)
{
    int s = blockIdx.x;
    int tid = threadIdx.x;
    const float* row = kv + (long)s * LATENT;
    float* out = kfull + (long)s * LATENT;
    __shared__ float red[256];
    float ss = 0.f;
    for (int i = tid; i < KV_LORA; i += 256) { float v = row[i]; ss += v * v; }
    red[tid] = ss; __syncthreads();
    for (int st = 128; st > 0; st >>= 1) {
        if (tid < st) red[tid] += red[tid + st];
        __syncthreads();
    }
    float r = rsqrtf(red[0] / (float)KV_LORA + 1e-6f);
    for (int i = tid; i < KV_LORA; i += 256) out[i] = row[i] * r * lnw[i];
    if (tid < ROPE_D) {
        int j = tid;
        float x = row[KV_LORA + j];
        float rot = (j < 32) ? -row[KV_LORA + j + 32] : row[KV_LORA + j - 32];
        out[KV_LORA + j] = x * cosb[s * ROPE_D + j] + rot * sinb[s * ROPE_D + j];
    }
}

// ---------------- rope(q_pe) -> q_full[..., 512:576] ----------------
__global__ void rope_qpe_k(const float* __restrict__ q,
                           const float* __restrict__ cosb, const float* __restrict__ sinb,
                           float* __restrict__ qfull)
{
    int s = blockIdx.x;
    int h = blockIdx.y;
    int j = threadIdx.x;   // 0..63
    const float* x = q + (long)s * QBN + h * Q_HEAD + NOPE_D;
    float v = x[j];
    float rot = (j < 32) ? -x[j + 32] : x[j - 32];
    qfull[((long)h * S_LEN + s) * LATENT + KV_LORA + j] =
        v * cosb[s * ROPE_D + j] + rot * sinb[s * ROPE_D + j];
}

// ---------------- causal softmax over score rows ----------------
__global__ void softmax_causal_k(float* __restrict__ scores)
{
    int q = blockIdx.x;
    int h = blockIdx.y;
    int tid = threadIdx.x;
    float* row = scores + ((long)h * S_LEN + q) * S_LEN;
    int n = q + 1;
    __shared__ float red[256];

    float mx = -3.4e38f;
    for (int i = tid; i < n; i += 256) mx = fmaxf(mx, row[i]);
    red[tid] = mx; __syncthreads();
    for (int st = 128; st > 0; st >>= 1) {
        if (tid < st) red[tid] = fmaxf(red[tid], red[tid + st]);
        __syncthreads();
    }
    mx = red[0];
    __syncthreads();

    float sum = 0.f;
    for (int i = tid; i < n; i += 256) {
        float e = expf(row[i] - mx);
        row[i] = e;
        sum += e;
    }
    red[tid] = sum; __syncthreads();
    for (int st = 128; st > 0; st >>= 1) {
        if (tid < st) red[tid] += red[tid + st];
        __syncthreads();
    }
    float inv = 1.f / red[0];
    for (int i = tid; i < n; i += 256) row[i] *= inv;
    for (int i = n + tid; i < S_LEN; i += 256) row[i] = 0.f;
}

// ---------------- launch helpers ----------------
static void gemm_nn(const float* A, const float* B, float* C,
                    int M, int N, int K, int lda, int ldb, int ldc,
                    long sA, long sB, long sC, int batch, float alpha)
{
    dim3 grid((N + 127) / 128, M / 128, batch);
    gemm_nn_k<<<grid, 256>>>(A, B, C, M, N, K, lda, ldb, ldc, sA, sB, sC, alpha);
}
static void gemm_nt(const float* A, const float* B, float* C,
                    int M, int N, int K, int lda, int ldb, int ldc,
                    long sA, long sB, long sC, int batch, float alpha)
{
    dim3 grid((N + 127) / 128, M / 128, batch);
    gemm_nt_k<<<grid, 256>>>(A, B, C, M, N, K, lda, ldb, ldc, sA, sB, sC, alpha);
}

extern "C" void kernel_launch(void* const* d_in, const int* in_sizes, int n_in,
                              void* d_out, int out_size)
{
    const float* h      = (const float*)d_in[0];   // (1,S,D)
    const float* cosb   = (const float*)d_in[1];   // (S,64)
    const float* sinb   = (const float*)d_in[2];   // (S,64)
    const float* q_a_w  = (const float*)d_in[3];   // (D, Q_LORA)
    const float* q_a_ln = (const float*)d_in[4];   // (Q_LORA)
    const float* q_b_w  = (const float*)d_in[5];   // (Q_LORA, QBN)
    const float* kv_a_w = (const float*)d_in[6];   // (D, 576)
    const float* kv_ln  = (const float*)d_in[7];   // (512)
    const float* kc_w   = (const float*)d_in[8];   // (H,128,512)
    const float* vc_w   = (const float*)d_in[9];   // (H,512,128)
    const float* o_w    = (const float*)d_in[10];  // (OUTW, D)
    float* out = (float*)d_out;

    float *p_qa, *p_q, *p_kv, *p_kfull, *p_qfull, *p_veff, *p_scores, *p_bigout;
    cudaGetSymbolAddress((void**)&p_qa,     g_qa);
    cudaGetSymbolAddress((void**)&p_q,      g_q);
    cudaGetSymbolAddress((void**)&p_kv,     g_kv);
    cudaGetSymbolAddress((void**)&p_kfull,  g_kfull);
    cudaGetSymbolAddress((void**)&p_qfull,  g_qfull);
    cudaGetSymbolAddress((void**)&p_veff,   g_veff);
    cudaGetSymbolAddress((void**)&p_scores, g_scores);
    cudaGetSymbolAddress((void**)&p_bigout, g_bigout);

    double mscale = 0.1 * log(40.0) + 1.0;
    const float SCALE = (float)(pow((double)Q_HEAD, -0.5) * mscale * mscale);

    // 1) qa = h @ q_a_w
    gemm_nn(h, q_a_w, p_qa, S_LEN, Q_LORA, D_MODEL, D_MODEL, Q_LORA, Q_LORA, 0, 0, 0, 1, 1.f);
    // 2) rmsnorm(qa) in place
    rmsnorm_rows_k<<<S_LEN, 256>>>(p_qa, q_a_ln, Q_LORA);
    // 3) q = qa_n @ q_b_w
    gemm_nn(p_qa, q_b_w, p_q, S_LEN, QBN, Q_LORA, Q_LORA, QBN, QBN, 0, 0, 0, 1, 1.f);
    // 4) kv = h @ kv_a_w
    gemm_nn(h, kv_a_w, p_kv, S_LEN, LATENT, D_MODEL, D_MODEL, LATENT, LATENT, 0, 0, 0, 1, 1.f);
    // 5) k_full = rmsnorm(latent) || rope(k_pe)
    build_kfull_k<<<S_LEN, 256>>>(p_kv, kv_ln, cosb, sinb, p_kfull);
    // 6) q_nope_abs (batched over heads): q_full[h][s][0:512]
    gemm_nn(p_q, kc_w, p_qfull,
            S_LEN, KV_LORA, NOPE_D,
            QBN, KV_LORA, LATENT,
            (long)Q_HEAD, (long)NOPE_D * KV_LORA, (long)S_LEN * LATENT,
            H_HEADS, 1.f);
    // 7) rope(q_pe) -> q_full[h][s][512:576]
    {
        dim3 grid(S_LEN, H_HEADS);
        rope_qpe_k<<<grid, 64>>>(p_q, cosb, sinb, p_qfull);
    }
    // 8) V_eff[h] = latent @ vc_w[h]  (latent = k_full[:, :512], row stride 576)
    gemm_nn(p_kfull, vc_w, p_veff,
            S_LEN, VDIM, KV_LORA,
            LATENT, VDIM, VDIM,
            0, (long)KV_LORA * VDIM, (long)S_LEN * VDIM,
            H_HEADS, 1.f);
    // 9) scores[h] = SCALE * q_full[h] @ k_full^T
    gemm_nt(p_qfull, p_kfull, p_scores,
            S_LEN, S_LEN, LATENT,
            LATENT, LATENT, S_LEN,
            (long)S_LEN * LATENT, 0, (long)S_LEN * S_LEN,
            H_HEADS, SCALE);
    // 10) causal softmax
    {
        dim3 grid(S_LEN, H_HEADS);
        softmax_causal_k<<<grid, 256>>>(p_scores);
    }
    // 11) big_out[:, h*128:(h+1)*128] = probs[h] @ V_eff[h]
    gemm_nn(p_scores, p_veff, p_bigout,
            S_LEN, VDIM, S_LEN,
            S_LEN, VDIM, OUTW,
            (long)S_LEN * S_LEN, (long)S_LEN * VDIM, (long)VDIM,
            H_HEADS, 1.f);
    // 12) out = big_out @ o_w
    gemm_nn(p_bigout, o_w, out, S_LEN, D_MODEL, OUTW, OUTW, D_MODEL, D_MODEL, 0, 0, 0, 1, 1.f);
}

// round 3
// speedup vs baseline: 2.0000x; 2.0000x over previous
#include <cuda_runtime.h>
#include <cuda_bf16.h>
#include <math.h>
#include <stdint.h>

// ---------------- problem constants ----------------
#define S_LEN   1024
#define D_MODEL 5120
#define H_HEADS 128
#define Q_LORA  1536
#define KV_LORA 512
#define ROPE_D  64
#define NOPE_D  128
#define VDIM    128
#define Q_HEAD  192          // NOPE + ROPE
#define LATENT  576          // KV_LORA + ROPE
#define QBN     24576        // H * Q_HEAD
#define OUTW    16384        // H * VDIM

typedef __nv_bfloat16 bf16;

// ---------------- scratch (device globals; no allocation) ----------------
// bf16 split operands (A-style: [hi|hi|lo] along K; B-style: [hi;lo;hi] rows)
__device__ __align__(16) bf16 g_h2    [(size_t)S_LEN * 3 * D_MODEL];          // 31.5 MB
__device__ __align__(16) bf16 g_qaw2  [(size_t)3 * D_MODEL * Q_LORA];         // 47 MB
__device__ __align__(16) bf16 g_qa2   [(size_t)S_LEN * 3 * Q_LORA];           // 9.4 MB
__device__ __align__(16) bf16 g_qbw2  [(size_t)3 * Q_LORA * QBN];             // 227 MB
__device__ __align__(16) bf16 g_qn2   [(size_t)H_HEADS * S_LEN * 3 * NOPE_D]; // 100 MB
__device__ __align__(16) bf16 g_kc2   [(size_t)H_HEADS * 3 * NOPE_D * KV_LORA]; // 50 MB
__device__ __align__(16) bf16 g_kvaw2 [(size_t)3 * D_MODEL * LATENT];         // 17.7 MB
__device__ __align__(16) bf16 g_lat2  [(size_t)S_LEN * 3 * KV_LORA];          // 3 MB
__device__ __align__(16) bf16 g_kT2   [(size_t)3 * LATENT * S_LEN];           // 3.5 MB
__device__ __align__(16) bf16 g_vc2   [(size_t)H_HEADS * 3 * KV_LORA * VDIM]; // 50 MB
__device__ __align__(16) bf16 g_qfull2[(size_t)H_HEADS * S_LEN * 3 * LATENT]; // 453 MB
__device__ __align__(16) bf16 g_veff2 [(size_t)H_HEADS * 3 * S_LEN * VDIM];   // 100 MB
__device__ __align__(16) bf16 g_probs2[(size_t)H_HEADS * S_LEN * 3 * S_LEN];  // 806 MB
__device__ __align__(16) bf16 g_bigo2 [(size_t)S_LEN * 3 * OUTW];             // 100 MB
__device__ __align__(16) bf16 g_ow2   [(size_t)3 * OUTW * D_MODEL];           // 503 MB
// fp32 intermediates
__device__ __align__(16) float g_qa   [(size_t)S_LEN * Q_LORA];
__device__ __align__(16) float g_q    [(size_t)S_LEN * QBN];
__device__ __align__(16) float g_kv   [(size_t)S_LEN * LATENT];
__device__ __align__(16) float g_kfull[(size_t)S_LEN * LATENT];
__device__ __align__(16) float g_qfull[(size_t)H_HEADS * S_LEN * LATENT];
__device__ __align__(16) float g_veff [(size_t)H_HEADS * S_LEN * VDIM];
__device__ __align__(16) float g_scores[(size_t)H_HEADS * S_LEN * S_LEN];
__device__ __align__(16) float g_bigout[(size_t)S_LEN * OUTW];

// ---------------- PTX helpers ----------------
__device__ __forceinline__ void cp_async16(uint32_t dst, const void* src, bool pred) {
    int sz = pred ? 16 : 0;
    asm volatile("cp.async.cg.shared.global [%0], [%1], 16, %2;\n"
                 :: "r"(dst), "l"(src), "r"(sz));
}
__device__ __forceinline__ void cp_commit() {
    asm volatile("cp.async.commit_group;\n" ::: "memory");
}
__device__ __forceinline__ void ldsm_x4(uint32_t* r, uint32_t addr) {
    asm volatile("ldmatrix.sync.aligned.m8n8.x4.shared.b16 {%0,%1,%2,%3}, [%4];\n"
                 : "=r"(r[0]), "=r"(r[1]), "=r"(r[2]), "=r"(r[3]) : "r"(addr));
}
__device__ __forceinline__ void ldsm_x4_t(uint32_t* r, uint32_t addr) {
    asm volatile("ldmatrix.sync.aligned.m8n8.x4.trans.shared.b16 {%0,%1,%2,%3}, [%4];\n"
                 : "=r"(r[0]), "=r"(r[1]), "=r"(r[2]), "=r"(r[3]) : "r"(addr));
}
__device__ __forceinline__ void mma_bf16(float* d, const uint32_t* a, const uint32_t* b) {
    asm volatile("mma.sync.aligned.m16n8k16.row.col.f32.bf16.bf16.f32 "
                 "{%0,%1,%2,%3},{%4,%5,%6,%7},{%8,%9},{%0,%1,%2,%3};\n"
                 : "+f"(d[0]), "+f"(d[1]), "+f"(d[2]), "+f"(d[3])
                 : "r"(a[0]), "r"(a[1]), "r"(a[2]), "r"(a[3]), "r"(b[0]), "r"(b[1]));
}

// ---------------- bf16 tensor-core GEMM: 128x128x32, 256 thr, NN ----------------
#define BM 128
#define BN 128
#define BK 32
#define ASTR (BK + 8)    // 40 bf16 = 80B row stride
#define BSTR (BN + 8)    // 136 bf16 = 272B row stride

__global__ void __launch_bounds__(256) gemm_bf16_k(
    const bf16* __restrict__ A, const bf16* __restrict__ B, float* __restrict__ C,
    int M, int N, int K, int lda, int ldb, int ldc,
    long sA, long sB, long sC, float alpha)
{
    A += (long)blockIdx.z * sA;
    B += (long)blockIdx.z * sB;
    C += (long)blockIdx.z * sC;

    __shared__ __align__(16) bf16 As[2][BM][ASTR];
    __shared__ __align__(16) bf16 Bs[2][BK][BSTR];

    const int tid  = threadIdx.x;
    const int lane = tid & 31;
    const int warp = tid >> 5;
    const int wm   = warp >> 1;   // 0..3
    const int wn   = warp & 1;    // 0..1
    const int m0   = blockIdx.y * BM;
    const int n0   = blockIdx.x * BN;

    float acc[2][8][4];
#pragma unroll
    for (int a = 0; a < 2; a++)
#pragma unroll
        for (int b = 0; b < 8; b++)
#pragma unroll
            for (int c = 0; c < 4; c++) acc[a][b][c] = 0.f;

    const int ktiles = K / BK;

    // ---- stage loaders ----
    auto load_tiles = [&](int buf, int kt) {
#pragma unroll
        for (int i = 0; i < 2; i++) {           // A: 512 16B-segments
            int seg = tid + 256 * i;
            int r = seg >> 2, c = (seg & 3) * 8;
            uint32_t dst = (uint32_t)__cvta_generic_to_shared(&As[buf][r][c]);
            const bf16* src = A + (long)(m0 + r) * lda + kt + c;
            cp_async16(dst, src, true);
        }
#pragma unroll
        for (int i = 0; i < 2; i++) {           // B: 512 16B-segments
            int seg = tid + 256 * i;
            int r = seg >> 4, c = (seg & 15) * 8;
            uint32_t dst = (uint32_t)__cvta_generic_to_shared(&Bs[buf][r][c]);
            bool ok = (n0 + c) < N;
            const bf16* src = ok ? (B + (long)(kt + r) * ldb + n0 + c) : B;
            cp_async16(dst, src, ok);
        }
    };

    load_tiles(0, 0);
    cp_commit();

    for (int t = 0; t < ktiles; t++) {
        int buf = t & 1;
        if (t + 1 < ktiles) {
            load_tiles(buf ^ 1, (t + 1) * BK);
            cp_commit();
            asm volatile("cp.async.wait_group 1;\n" ::: "memory");
        } else {
            asm volatile("cp.async.wait_group 0;\n" ::: "memory");
        }
        __syncthreads();

#pragma unroll
        for (int kk = 0; kk < 2; kk++) {
            uint32_t af[2][4];
#pragma unroll
            for (int mt = 0; mt < 2; mt++) {
                uint32_t addr = (uint32_t)__cvta_generic_to_shared(
                    &As[buf][wm * 32 + mt * 16 + (lane & 15)][kk * 16 + (lane >> 4) * 8]);
                ldsm_x4(af[mt], addr);
            }
            uint32_t bfr[4][4];
#pragma unroll
            for (int np = 0; np < 4; np++) {
                uint32_t addr = (uint32_t)__cvta_generic_to_shared(
                    &Bs[buf][kk * 16 + (lane & 15)][wn * 64 + np * 16 + (lane >> 4) * 8]);
                ldsm_x4_t(bfr[np], addr);
            }
#pragma unroll
            for (int mt = 0; mt < 2; mt++)
#pragma unroll
                for (int nt = 0; nt < 8; nt++)
                    mma_bf16(acc[mt][nt], af[mt], &bfr[nt >> 1][(nt & 1) * 2]);
        }
        __syncthreads();
    }

    // ---- epilogue ----
    const int r  = lane >> 2;
    const int c2 = (lane & 3) * 2;
#pragma unroll
    for (int mt = 0; mt < 2; mt++) {
#pragma unroll
        for (int nt = 0; nt < 8; nt++) {
            int m = m0 + wm * 32 + mt * 16 + r;
            int n = n0 + wn * 64 + nt * 8 + c2;
            if (n < N) {
                C[(long)m * ldc + n]       = alpha * acc[mt][nt][0];
                C[(long)m * ldc + n + 1]   = alpha * acc[mt][nt][1];
                C[(long)(m + 8) * ldc + n]     = alpha * acc[mt][nt][2];
                C[(long)(m + 8) * ldc + n + 1] = alpha * acc[mt][nt][3];
            }
        }
    }
}

// ---------------- fp32 -> split-bf16 converters ----------------
__device__ __forceinline__ void split_bf16(float x, bf16& hi, bf16& lo) {
    hi = __float2bfloat16(x);
    lo = __float2bfloat16(x - __bfloat162float(hi));
}

// A-style: src (M x K fp32, row stride lda, batch stride ssrc)
//       -> dst (M x 3K bf16 dense): row = [hi(K) | hi(K) | lo(K)]
__global__ void convA_k(const float* __restrict__ src, bf16* __restrict__ dst,
                        int M, int K, int lda, long ssrc)
{
    src += (long)blockIdx.z * ssrc;
    dst += (long)blockIdx.z * M * 3 * K;
    long total = (long)M * K;
    for (long idx = (long)blockIdx.x * blockDim.x + threadIdx.x; idx < total;
         idx += (long)gridDim.x * blockDim.x) {
        int m = (int)(idx / K), k = (int)(idx % K);
        float x = src[(long)m * lda + k];
        bf16 hi, lo; split_bf16(x, hi, lo);
        bf16* row = dst + (long)m * 3 * K;
        row[k] = hi; row[K + k] = hi; row[2 * K + k] = lo;
    }
}

// B-style: src (K x N fp32, row stride ldb, batch stride ssrc)
//       -> dst (3K x N bf16 dense): rows = [hi(K) ; lo(K) ; hi(K)]
__global__ void convB_k(const float* __restrict__ src, bf16* __restrict__ dst,
                        int K, int N, int ldb, long ssrc)
{
    src += (long)blockIdx.z * ssrc;
    dst += (long)blockIdx.z * 3 * K * N;
    long total = (long)K * N;
    for (long idx = (long)blockIdx.x * blockDim.x + threadIdx.x; idx < total;
         idx += (long)gridDim.x * blockDim.x) {
        int k = (int)(idx / N), n = (int)(idx % N);
        float x = src[(long)k * ldb + n];
        bf16 hi, lo; split_bf16(x, hi, lo);
        dst[(long)k * N + n] = hi;
        dst[((long)K + k) * N + n] = lo;
        dst[((long)2 * K + k) * N + n] = hi;
    }
}

// B-style from transposed source: src is (N x K fp32, row stride lds);
// logical B[k][n] = src[n][k]  ->  dst (3K x N bf16 dense) [hi;lo;hi]
__global__ void convBt_k(const float* __restrict__ src, bf16* __restrict__ dst,
                         int K, int N, int lds)
{
    long total = (long)K * N;
    for (long idx = (long)blockIdx.x * blockDim.x + threadIdx.x; idx < total;
         idx += (long)gridDim.x * blockDim.x) {
        int k = (int)(idx / N), n = (int)(idx % N);
        float x = src[(long)n * lds + k];
        bf16 hi, lo; split_bf16(x, hi, lo);
        dst[(long)k * N + n] = hi;
        dst[((long)K + k) * N + n] = lo;
        dst[((long)2 * K + k) * N + n] = hi;
    }
}

// ---------------- in-place row rmsnorm ----------------
__global__ void rmsnorm_rows_k(float* x, const float* __restrict__ w, int W)
{
    int row = blockIdx.x;
    float* p = x + (long)row * W;
    __shared__ float red[256];
    int tid = threadIdx.x;
    float ss = 0.f;
    for (int i = tid; i < W; i += 256) { float v = p[i]; ss += v * v; }
    red[tid] = ss; __syncthreads();
    for (int st = 128; st > 0; st >>= 1) {
        if (tid < st) red[tid] += red[tid + st];
        __syncthreads();
    }
    float r = rsqrtf(red[0] / (float)W + 1e-6f);
    for (int i = tid; i < W; i += 256) p[i] = p[i] * r * w[i];
}

// ---------------- k_full: rmsnorm(latent) || rope(k_pe) ----------------
__global__ void build_kfull_k(const float* __restrict__ kv, const float* __restrict__ lnw,
                              const float* __restrict__ cosb, const float* __restrict__ sinb,
                              float* __restrict__ kfull)
{
    int s = blockIdx.x;
    int tid = threadIdx.x;
    const float* row = kv + (long)s * LATENT;
    float* out = kfull + (long)s * LATENT;
    __shared__ float red[256];
    float ss = 0.f;
    for (int i = tid; i < KV_LORA; i += 256) { float v = row[i]; ss += v * v; }
    red[tid] = ss; __syncthreads();
    for (int st = 128; st > 0; st >>= 1) {
        if (tid < st) red[tid] += red[tid + st];
        __syncthreads();
    }
    float r = rsqrtf(red[0] / (float)KV_LORA + 1e-6f);
    for (int i = tid; i < KV_LORA; i += 256) out[i] = row[i] * r * lnw[i];
    if (tid < ROPE_D) {
        int j = tid;
        float x = row[KV_LORA + j];
        float rot = (j < 32) ? -row[KV_LORA + j + 32] : row[KV_LORA + j - 32];
        out[KV_LORA + j] = x * cosb[s * ROPE_D + j] + rot * sinb[s * ROPE_D + j];
    }
}

// ---------------- rope(q_pe) -> q_full[..., 512:576] ----------------
__global__ void rope_qpe_k(const float* __restrict__ q,
                           const float* __restrict__ cosb, const float* __restrict__ sinb,
                           float* __restrict__ qfull)
{
    int s = blockIdx.x;
    int h = blockIdx.y;
    int j = threadIdx.x;   // 0..63
    const float* x = q + (long)s * QBN + h * Q_HEAD + NOPE_D;
    float v = x[j];
    float rot = (j < 32) ? -x[j + 32] : x[j - 32];
    qfull[((long)h * S_LEN + s) * LATENT + KV_LORA + j] =
        v * cosb[s * ROPE_D + j] + rot * sinb[s * ROPE_D + j];
}

// ---------------- causal softmax fused with split-bf16 A-style output ----------------
// probs2[h][s] row layout (3*S_LEN): [hi(1024) | hi(1024) | lo(1024)]
__global__ void softmax_probs2_k(const float* __restrict__ scores, bf16* __restrict__ probs2)
{
    int q = blockIdx.x;
    int h = blockIdx.y;
    int tid = threadIdx.x;
    const float* row = scores + ((long)h * S_LEN + q) * S_LEN;
    bf16* orow = probs2 + ((long)h * S_LEN + q) * (3 * S_LEN);
    int n = q + 1;
    __shared__ float red[256];

    float v[4];
    float mx = -3.4e38f;
#pragma unroll
    for (int j = 0; j < 4; j++) {
        int i = tid + 256 * j;
        v[j] = (i < n) ? row[i] : -3.4e38f;
        mx = fmaxf(mx, v[j]);
    }
    red[tid] = mx; __syncthreads();
    for (int st = 128; st > 0; st >>= 1) {
        if (tid < st) red[tid] = fmaxf(red[tid], red[tid + st]);
        __syncthreads();
    }
    mx = red[0];
    __syncthreads();

    float sum = 0.f;
#pragma unroll
    for (int j = 0; j < 4; j++) {
        int i = tid + 256 * j;
        v[j] = (i < n) ? __expf(v[j] - mx) : 0.f;
        sum += v[j];
    }
    red[tid] = sum; __syncthreads();
    for (int st = 128; st > 0; st >>= 1) {
        if (tid < st) red[tid] += red[tid + st];
        __syncthreads();
    }
    float inv = 1.f / red[0];
#pragma unroll
    for (int j = 0; j < 4; j++) {
        int i = tid + 256 * j;
        float p = v[j] * inv;
        bf16 hi, lo; split_bf16(p, hi, lo);
        orow[i] = hi;
        orow[S_LEN + i] = hi;
        orow[2 * S_LEN + i] = lo;
    }
}

// ---------------- host-side launchers ----------------
static void gemm(const bf16* A, const bf16* B, float* C,
                 int M, int N, int K, int lda, int ldb, int ldc,
                 long sA, long sB, long sC, int batch, float alpha)
{
    dim3 grid((N + BN - 1) / BN, M / BM, batch);
    gemm_bf16_k<<<grid, 256>>>(A, B, C, M, N, K, lda, ldb, ldc, sA, sB, sC, alpha);
}
static void convA(const float* src, bf16* dst, int M, int K, int lda, long ssrc, int batch)
{
    long total = (long)M * K;
    int blocks = (int)((total + 255) / 256);
    if (blocks > 4096) blocks = 4096;
    convA_k<<<dim3(blocks, 1, batch), 256>>>(src, dst, M, K, lda, ssrc);
}
static void convB(const float* src, bf16* dst, int K, int N, int ldb, long ssrc, int batch)
{
    long total = (long)K * N;
    int blocks = (int)((total + 255) / 256);
    if (blocks > 4096) blocks = 4096;
    convB_k<<<dim3(blocks, 1, batch), 256>>>(src, dst, K, N, ldb, ssrc);
}

extern "C" void kernel_launch(void* const* d_in, const int* in_sizes, int n_in,
                              void* d_out, int out_size)
{
    const float* h      = (const float*)d_in[0];   // (1,S,D)
    const float* cosb   = (const float*)d_in[1];   // (S,64)
    const float* sinb   = (const float*)d_in[2];   // (S,64)
    const float* q_a_w  = (const float*)d_in[3];   // (D, Q_LORA)
    const float* q_a_ln = (const float*)d_in[4];   // (Q_LORA)
    const float* q_b_w  = (const float*)d_in[5];   // (Q_LORA, QBN)
    const float* kv_a_w = (const float*)d_in[6];   // (D, 576)
    const float* kv_ln  = (const float*)d_in[7];   // (512)
    const float* kc_w   = (const float*)d_in[8];   // (H,128,512)
    const float* vc_w   = (const float*)d_in[9];   // (H,512,128)
    const float* o_w    = (const float*)d_in[10];  // (OUTW, D)
    float* out = (float*)d_out;

    bf16 *p_h2, *p_qaw2, *p_qa2, *p_qbw2, *p_qn2, *p_kc2, *p_kvaw2, *p_lat2, *p_kT2;
    bf16 *p_vc2, *p_qfull2, *p_veff2, *p_probs2, *p_bigo2, *p_ow2;
    float *p_qa, *p_q, *p_kv, *p_kfull, *p_qfull, *p_veff, *p_scores, *p_bigout;
    cudaGetSymbolAddress((void**)&p_h2,     g_h2);
    cudaGetSymbolAddress((void**)&p_qaw2,   g_qaw2);
    cudaGetSymbolAddress((void**)&p_qa2,    g_qa2);
    cudaGetSymbolAddress((void**)&p_qbw2,   g_qbw2);
    cudaGetSymbolAddress((void**)&p_qn2,    g_qn2);
    cudaGetSymbolAddress((void**)&p_kc2,    g_kc2);
    cudaGetSymbolAddress((void**)&p_kvaw2,  g_kvaw2);
    cudaGetSymbolAddress((void**)&p_lat2,   g_lat2);
    cudaGetSymbolAddress((void**)&p_kT2,    g_kT2);
    cudaGetSymbolAddress((void**)&p_vc2,    g_vc2);
    cudaGetSymbolAddress((void**)&p_qfull2, g_qfull2);
    cudaGetSymbolAddress((void**)&p_veff2,  g_veff2);
    cudaGetSymbolAddress((void**)&p_probs2, g_probs2);
    cudaGetSymbolAddress((void**)&p_bigo2,  g_bigo2);
    cudaGetSymbolAddress((void**)&p_ow2,    g_ow2);
    cudaGetSymbolAddress((void**)&p_qa,     g_qa);
    cudaGetSymbolAddress((void**)&p_q,      g_q);
    cudaGetSymbolAddress((void**)&p_kv,     g_kv);
    cudaGetSymbolAddress((void**)&p_kfull,  g_kfull);
    cudaGetSymbolAddress((void**)&p_qfull,  g_qfull);
    cudaGetSymbolAddress((void**)&p_veff,   g_veff);
    cudaGetSymbolAddress((void**)&p_scores, g_scores);
    cudaGetSymbolAddress((void**)&p_bigout, g_bigout);

    double mscale = 0.1 * log(40.0) + 1.0;
    const float SCALE = (float)(pow((double)Q_HEAD, -0.5) * mscale * mscale);

    // ---- weight / input conversions (every call; no caching allowed) ----
    convA(h,      p_h2,    S_LEN, D_MODEL, D_MODEL, 0, 1);
    convB(q_a_w,  p_qaw2,  D_MODEL, Q_LORA, Q_LORA, 0, 1);
    convB(kv_a_w, p_kvaw2, D_MODEL, LATENT, LATENT, 0, 1);
    convB(q_b_w,  p_qbw2,  Q_LORA, QBN, QBN, 0, 1);
    convB(kc_w,   p_kc2,   NOPE_D, KV_LORA, KV_LORA, (long)NOPE_D * KV_LORA, H_HEADS);
    convB(vc_w,   p_vc2,   KV_LORA, VDIM, VDIM, (long)KV_LORA * VDIM, H_HEADS);
    convB(o_w,    p_ow2,   OUTW, D_MODEL, D_MODEL, 0, 1);

    // 1) qa = h @ q_a_w
    gemm(p_h2, p_qaw2, p_qa, S_LEN, Q_LORA, 3 * D_MODEL,
         3 * D_MODEL, Q_LORA, Q_LORA, 0, 0, 0, 1, 1.f);
    // 2) rmsnorm(qa) in place, then split
    rmsnorm_rows_k<<<S_LEN, 256>>>(p_qa, q_a_ln, Q_LORA);
    convA(p_qa, p_qa2, S_LEN, Q_LORA, Q_LORA, 0, 1);
    // 3) q = qa_n @ q_b_w
    gemm(p_qa2, p_qbw2, p_q, S_LEN, QBN, 3 * Q_LORA,
         3 * Q_LORA, QBN, QBN, 0, 0, 0, 1, 1.f);
    // 4) kv = h @ kv_a_w
    gemm(p_h2, p_kvaw2, p_kv, S_LEN, LATENT, 3 * D_MODEL,
         3 * D_MODEL, LATENT, LATENT, 0, 0, 0, 1, 1.f);
    // 5) k_full = rmsnorm(latent) || rope(k_pe); split latent + transposed k_full
    build_kfull_k<<<S_LEN, 256>>>(p_kv, kv_ln, cosb, sinb, p_kfull);
    convA(p_kfull, p_lat2, S_LEN, KV_LORA, LATENT, 0, 1);
    {
        long total = (long)LATENT * S_LEN;
        int blocks = (int)((total + 255) / 256);
        convBt_k<<<blocks, 256>>>(p_kfull, p_kT2, LATENT, S_LEN, LATENT);
    }
    // 6) q_nope slices -> split; q_full[h][:, :512] = qn[h] @ kc_w[h]
    convA(p_q, p_qn2, S_LEN, NOPE_D, QBN, (long)Q_HEAD, H_HEADS);
    gemm(p_qn2, p_kc2, p_qfull,
         S_LEN, KV_LORA, 3 * NOPE_D,
         3 * NOPE_D, KV_LORA, LATENT,
         (long)S_LEN * 3 * NOPE_D, (long)3 * NOPE_D * KV_LORA, (long)S_LEN * LATENT,
         H_HEADS, 1.f);
    // 7) rope(q_pe) -> q_full[h][:, 512:576]; then split q_full
    {
        dim3 grid(S_LEN, H_HEADS);
        rope_qpe_k<<<grid, 64>>>(p_q, cosb, sinb, p_qfull);
    }
    convA(p_qfull, p_qfull2, S_LEN, LATENT, LATENT, (long)S_LEN * LATENT, H_HEADS);
    // 8) V_eff[h] = latent @ vc_w[h]; then split (B-style)
    gemm(p_lat2, p_vc2, p_veff,
         S_LEN, VDIM, 3 * KV_LORA,
         3 * KV_LORA, VDIM, VDIM,
         0, (long)3 * KV_LORA * VDIM, (long)S_LEN * VDIM,
         H_HEADS, 1.f);
    convB(p_veff, p_veff2, S_LEN, VDIM, VDIM, (long)S_LEN * VDIM, H_HEADS);
    // 9) scores[h] = SCALE * q_full[h] @ k_full^T
    gemm(p_qfull2, p_kT2, p_scores,
         S_LEN, S_LEN, 3 * LATENT,
         3 * LATENT, S_LEN, S_LEN,
         (long)S_LEN * 3 * LATENT, 0, (long)S_LEN * S_LEN,
         H_HEADS, SCALE);
    // 10) causal softmax fused with split-bf16 output
    {
        dim3 grid(S_LEN, H_HEADS);
        softmax_probs2_k<<<grid, 256>>>(p_scores, p_probs2);
    }
    // 11) big_out[:, h*128:(h+1)*128] = probs[h] @ V_eff[h]
    gemm(p_probs2, p_veff2, p_bigout,
         S_LEN, VDIM, 3 * S_LEN,
         3 * S_LEN, VDIM, OUTW,
         (long)S_LEN * 3 * S_LEN, (long)3 * S_LEN * VDIM, (long)VDIM,
         H_HEADS, 1.f);
    // 12) out = big_out @ o_w
    convA(p_bigout, p_bigo2, S_LEN, OUTW, OUTW, 0, 1);
    gemm(p_bigo2, p_ow2, out, S_LEN, D_MODEL, 3 * OUTW,
         3 * OUTW, D_MODEL, D_MODEL, 0, 0, 0, 1, 1.f);
}

// round 5
// speedup vs baseline: 2.8939x; 1.4470x over previous
#include <cuda_runtime.h>
#include <cuda_bf16.h>
#include <math.h>
#include <stdint.h>

// ---------------- problem constants ----------------
#define S_LEN   1024
#define D_MODEL 5120
#define H_HEADS 128
#define Q_LORA  1536
#define KV_LORA 512
#define ROPE_D  64
#define NOPE_D  128
#define VDIM    128
#define Q_HEAD  192          // NOPE + ROPE
#define LATENT  576          // KV_LORA + ROPE
#define QBN     24576        // H * Q_HEAD
#define OUTW    16384        // H * VDIM

typedef __nv_bfloat16 bf16;

// ---------------- scratch (device globals; no allocation) ----------------
__device__ __align__(16) bf16 g_h2    [(size_t)S_LEN * 3 * D_MODEL];
__device__ __align__(16) bf16 g_qaw2  [(size_t)3 * D_MODEL * Q_LORA];
__device__ __align__(16) bf16 g_qa2   [(size_t)S_LEN * 3 * Q_LORA];
__device__ __align__(16) bf16 g_qbw2  [(size_t)3 * Q_LORA * QBN];
__device__ __align__(16) bf16 g_qn2   [(size_t)H_HEADS * S_LEN * 3 * NOPE_D];
__device__ __align__(16) bf16 g_kc2   [(size_t)H_HEADS * 3 * NOPE_D * KV_LORA];
__device__ __align__(16) bf16 g_kvaw2 [(size_t)3 * D_MODEL * LATENT];
__device__ __align__(16) bf16 g_lat2  [(size_t)S_LEN * 3 * KV_LORA];
__device__ __align__(16) bf16 g_kT2   [(size_t)3 * LATENT * S_LEN];
__device__ __align__(16) bf16 g_vc2   [(size_t)H_HEADS * 3 * KV_LORA * VDIM];
__device__ __align__(16) bf16 g_qfull2[(size_t)H_HEADS * S_LEN * 3 * LATENT];
// veff2[h]: (3*S, VDIM) interleaved rows [hi;lo;hi] per source row
__device__ __align__(16) bf16 g_veff2 [(size_t)H_HEADS * 3 * S_LEN * VDIM];
// probs2[h][q]: K-interleaved triples (hi,hi,lo) per k  -> width 3*S
__device__ __align__(16) bf16 g_probs2[(size_t)H_HEADS * S_LEN * 3 * S_LEN];
// bigo2: (S, 3*OUTW) A-style [hi|hi|lo]
__device__ __align__(16) bf16 g_bigo2 [(size_t)S_LEN * 3 * OUTW];
__device__ __align__(16) bf16 g_ow2   [(size_t)3 * OUTW * D_MODEL];
// fp32 intermediates
__device__ __align__(16) float g_qa   [(size_t)S_LEN * Q_LORA];
__device__ __align__(16) float g_q    [(size_t)S_LEN * QBN];
__device__ __align__(16) float g_kv   [(size_t)S_LEN * LATENT];
__device__ __align__(16) float g_kfull[(size_t)S_LEN * LATENT];
__device__ __align__(16) float g_scores[(size_t)H_HEADS * S_LEN * S_LEN];

// ---------------- PTX helpers ----------------
__device__ __forceinline__ void cp_async16(uint32_t dst, const void* src, bool pred) {
    int sz = pred ? 16 : 0;
    asm volatile("cp.async.cg.shared.global [%0], [%1], 16, %2;\n"
                 :: "r"(dst), "l"(src), "r"(sz));
}
__device__ __forceinline__ void cp_commit() {
    asm volatile("cp.async.commit_group;\n" ::: "memory");
}
__device__ __forceinline__ void ldsm_x4(uint32_t* r, uint32_t addr) {
    asm volatile("ldmatrix.sync.aligned.m8n8.x4.shared.b16 {%0,%1,%2,%3}, [%4];\n"
                 : "=r"(r[0]), "=r"(r[1]), "=r"(r[2]), "=r"(r[3]) : "r"(addr));
}
__device__ __forceinline__ void ldsm_x4_t(uint32_t* r, uint32_t addr) {
    asm volatile("ldmatrix.sync.aligned.m8n8.x4.trans.shared.b16 {%0,%1,%2,%3}, [%4];\n"
                 : "=r"(r[0]), "=r"(r[1]), "=r"(r[2]), "=r"(r[3]) : "r"(addr));
}
__device__ __forceinline__ void mma_bf16(float* d, const uint32_t* a, const uint32_t* b) {
    asm volatile("mma.sync.aligned.m16n8k16.row.col.f32.bf16.bf16.f32 "
                 "{%0,%1,%2,%3},{%4,%5,%6,%7},{%8,%9},{%0,%1,%2,%3};\n"
                 : "+f"(d[0]), "+f"(d[1]), "+f"(d[2]), "+f"(d[3])
                 : "r"(a[0]), "r"(a[1]), "r"(a[2]), "r"(a[3]), "r"(b[0]), "r"(b[1]));
}

__device__ __forceinline__ void split_bf16(float x, bf16& hi, bf16& lo) {
    hi = __float2bfloat16(x);
    lo = __float2bfloat16(x - __bfloat162float(hi));
}

// ---------------- templated bf16 tensor-core GEMM: 128x128x32 ----------------
// EPI: 0 = fp32 C;  1 = splitA [hi|hi|lo] (off2 = copy distance);
//      2 = splitB interleaved rows (3m:hi, 3m+1:lo, 3m+2:hi)
// TRI: lower-triangular tile launch (blockIdx.x linear over 36 tiles)
// KLIM: causal K limit  Keff = min(K, 3*(m0+BM))
#define BM 128
#define BN 128
#define BK 32
#define ASTR (BK + 8)
#define BSTR (BN + 8)

template<int EPI, int TRI, int KLIM>
__global__ void __launch_bounds__(256) gemm_t(
    const bf16* __restrict__ A, const bf16* __restrict__ B, void* __restrict__ Cv,
    int M, int N, int K, int lda, int ldb, int ldc,
    long sA, long sB, long sC, float alpha, int off2)
{
    int tm, tn;
    if (TRI) {
        int x = blockIdx.x;
        int r = (int)((-1.f + sqrtf(1.f + 8.f * (float)x)) * 0.5f);
        while ((r + 1) * (r + 2) / 2 <= x) ++r;
        while (r * (r + 1) / 2 > x) --r;
        tm = r; tn = x - r * (r + 1) / 2;
    } else { tn = blockIdx.x; tm = blockIdx.y; }

    const int m0 = tm * BM;
    const int n0 = tn * BN;
    A += (long)blockIdx.z * sA;
    B += (long)blockIdx.z * sB;

    int Keff = K;
    if (KLIM) { int lim = 3 * (m0 + BM); Keff = (lim < K) ? lim : K; }

    __shared__ __align__(16) bf16 As[2][BM][ASTR];
    __shared__ __align__(16) bf16 Bs[2][BK][BSTR];

    const int tid  = threadIdx.x;
    const int lane = tid & 31;
    const int warp = tid >> 5;
    const int wm   = warp >> 1;
    const int wn   = warp & 1;

    float acc[2][8][4];
#pragma unroll
    for (int a = 0; a < 2; a++)
#pragma unroll
        for (int b = 0; b < 8; b++)
#pragma unroll
            for (int c = 0; c < 4; c++) acc[a][b][c] = 0.f;

    const int ktiles = Keff / BK;

    auto load_tiles = [&](int buf, int kt) {
#pragma unroll
        for (int i = 0; i < 2; i++) {
            int seg = tid + 256 * i;
            int r = seg >> 2, c = (seg & 3) * 8;
            uint32_t dst = (uint32_t)__cvta_generic_to_shared(&As[buf][r][c]);
            const bf16* src = A + (long)(m0 + r) * lda + kt + c;
            cp_async16(dst, src, true);
        }
#pragma unroll
        for (int i = 0; i < 2; i++) {
            int seg = tid + 256 * i;
            int r = seg >> 4, c = (seg & 15) * 8;
            uint32_t dst = (uint32_t)__cvta_generic_to_shared(&Bs[buf][r][c]);
            bool ok = (n0 + c) < N;
            const bf16* src = ok ? (B + (long)(kt + r) * ldb + n0 + c) : B;
            cp_async16(dst, src, ok);
        }
    };

    load_tiles(0, 0);
    cp_commit();

    for (int t = 0; t < ktiles; t++) {
        int buf = t & 1;
        if (t + 1 < ktiles) {
            load_tiles(buf ^ 1, (t + 1) * BK);
            cp_commit();
            asm volatile("cp.async.wait_group 1;\n" ::: "memory");
        } else {
            asm volatile("cp.async.wait_group 0;\n" ::: "memory");
        }
        __syncthreads();

#pragma unroll
        for (int kk = 0; kk < 2; kk++) {
            uint32_t af[2][4];
#pragma unroll
            for (int mt = 0; mt < 2; mt++) {
                uint32_t addr = (uint32_t)__cvta_generic_to_shared(
                    &As[buf][wm * 32 + mt * 16 + (lane & 15)][kk * 16 + (lane >> 4) * 8]);
                ldsm_x4(af[mt], addr);
            }
            uint32_t bfr[4][4];
#pragma unroll
            for (int np = 0; np < 4; np++) {
                uint32_t addr = (uint32_t)__cvta_generic_to_shared(
                    &Bs[buf][kk * 16 + (lane & 15)][wn * 64 + np * 16 + (lane >> 4) * 8]);
                ldsm_x4_t(bfr[np], addr);
            }
#pragma unroll
            for (int mt = 0; mt < 2; mt++)
#pragma unroll
                for (int nt = 0; nt < 8; nt++)
                    mma_bf16(acc[mt][nt], af[mt], &bfr[nt >> 1][(nt & 1) * 2]);
        }
        __syncthreads();
    }

    // ---- epilogue ----
    const int r  = lane >> 2;
    const int c2 = (lane & 3) * 2;

    auto emit = [&](int m, int n, float v0, float v1) {
        v0 *= alpha; v1 *= alpha;
        if (EPI == 0) {
            float* C = (float*)Cv + (long)blockIdx.z * sC;
            C[(long)m * ldc + n]     = v0;
            C[(long)m * ldc + n + 1] = v1;
        } else if (EPI == 1) {
            bf16* C = (bf16*)Cv + (long)blockIdx.z * sC;
            bf16 h0, l0, h1, l1;
            split_bf16(v0, h0, l0); split_bf16(v1, h1, l1);
            __nv_bfloat162 hi2 = __nv_bfloat162(h0, h1);
            __nv_bfloat162 lo2 = __nv_bfloat162(l0, l1);
            long base = (long)m * ldc + n;
            *(__nv_bfloat162*)&C[base] = hi2;
            *(__nv_bfloat162*)&C[base + off2] = hi2;
            *(__nv_bfloat162*)&C[base + 2 * off2] = lo2;
        } else {
            bf16* C = (bf16*)Cv + (long)blockIdx.z * sC;
            bf16 h0, l0, h1, l1;
            split_bf16(v0, h0, l0); split_bf16(v1, h1, l1);
            __nv_bfloat162 hi2 = __nv_bfloat162(h0, h1);
            __nv_bfloat162 lo2 = __nv_bfloat162(l0, l1);
            *(__nv_bfloat162*)&C[(long)(3 * m)     * ldc + n] = hi2;
            *(__nv_bfloat162*)&C[(long)(3 * m + 1) * ldc + n] = lo2;
            *(__nv_bfloat162*)&C[(long)(3 * m + 2) * ldc + n] = hi2;
        }
    };

#pragma unroll
    for (int mt = 0; mt < 2; mt++) {
#pragma unroll
        for (int nt = 0; nt < 8; nt++) {
            int m = m0 + wm * 32 + mt * 16 + r;
            int n = n0 + wn * 64 + nt * 8 + c2;
            if (n < N) {
                emit(m,     n, acc[mt][nt][0], acc[mt][nt][1]);
                emit(m + 8, n, acc[mt][nt][2], acc[mt][nt][3]);
            }
        }
    }
}

// ---------------- vectorized converters ----------------
union BV4 { bf16 b[4]; uint2 u; };

// A-style: (M x K fp32) -> (M x 3K bf16): row = [hi | hi | lo]
__global__ void convA4_k(const float* __restrict__ src, bf16* __restrict__ dst,
                         int M, int K, int lda, long ssrc)
{
    src += (long)blockIdx.z * ssrc;
    dst += (long)blockIdx.z * M * 3 * K;
    int K4 = K >> 2;
    long total = (long)M * K4;
    for (long idx = (long)blockIdx.x * blockDim.x + threadIdx.x; idx < total;
         idx += (long)gridDim.x * blockDim.x) {
        int m = (int)(idx / K4), k = (int)(idx % K4) * 4;
        float4 x = *(const float4*)(src + (long)m * lda + k);
        BV4 hv, lv;
        split_bf16(x.x, hv.b[0], lv.b[0]);
        split_bf16(x.y, hv.b[1], lv.b[1]);
        split_bf16(x.z, hv.b[2], lv.b[2]);
        split_bf16(x.w, hv.b[3], lv.b[3]);
        bf16* row = dst + (long)m * 3 * K;
        *(uint2*)&row[k]         = hv.u;
        *(uint2*)&row[K + k]     = hv.u;
        *(uint2*)&row[2 * K + k] = lv.u;
    }
}

// B-style: (K x N fp32) -> (3K x N bf16): rows = [hi ; lo ; hi]
__global__ void convB4_k(const float* __restrict__ src, bf16* __restrict__ dst,
                         int K, int N, int ldb, long ssrc)
{
    src += (long)blockIdx.z * ssrc;
    dst += (long)blockIdx.z * 3 * K * N;
    int N4 = N >> 2;
    long total = (long)K * N4;
    for (long idx = (long)blockIdx.x * blockDim.x + threadIdx.x; idx < total;
         idx += (long)gridDim.x * blockDim.x) {
        int k = (int)(idx / N4), n = (int)(idx % N4) * 4;
        float4 x = *(const float4*)(src + (long)k * ldb + n);
        BV4 hv, lv;
        split_bf16(x.x, hv.b[0], lv.b[0]);
        split_bf16(x.y, hv.b[1], lv.b[1]);
        split_bf16(x.z, hv.b[2], lv.b[2]);
        split_bf16(x.w, hv.b[3], lv.b[3]);
        *(uint2*)&dst[(long)k * N + n]           = hv.u;
        *(uint2*)&dst[((long)K + k) * N + n]     = lv.u;
        *(uint2*)&dst[((long)2 * K + k) * N + n] = hv.u;
    }
}

// B-style from transposed source: src (N x K fp32), B[k][n]=src[n][k] -> [hi;lo;hi]
__global__ void convBt_k(const float* __restrict__ src, bf16* __restrict__ dst,
                         int K, int N, int lds)
{
    long total = (long)K * N;
    for (long idx = (long)blockIdx.x * blockDim.x + threadIdx.x; idx < total;
         idx += (long)gridDim.x * blockDim.x) {
        int k = (int)(idx / N), n = (int)(idx % N);
        float x = src[(long)n * lds + k];
        bf16 hi, lo; split_bf16(x, hi, lo);
        dst[(long)k * N + n] = hi;
        dst[((long)K + k) * N + n] = lo;
        dst[((long)2 * K + k) * N + n] = hi;
    }
}

// ---------------- in-place row rmsnorm ----------------
__global__ void rmsnorm_rows_k(float* x, const float* __restrict__ w, int W)
{
    int row = blockIdx.x;
    float* p = x + (long)row * W;
    __shared__ float red[256];
    int tid = threadIdx.x;
    float ss = 0.f;
    for (int i = tid; i < W; i += 256) { float v = p[i]; ss += v * v; }
    red[tid] = ss; __syncthreads();
    for (int st = 128; st > 0; st >>= 1) {
        if (tid < st) red[tid] += red[tid + st];
        __syncthreads();
    }
    float r = rsqrtf(red[0] / (float)W + 1e-6f);
    for (int i = tid; i < W; i += 256) p[i] = p[i] * r * w[i];
}

// ---------------- k_full: rmsnorm(latent) || rope(k_pe) ----------------
__global__ void build_kfull_k(const float* __restrict__ kv, const float* __restrict__ lnw,
                              const float* __restrict__ cosb, const float* __restrict__ sinb,
                              float* __restrict__ kfull)
{
    int s = blockIdx.x;
    int tid = threadIdx.x;
    const float* row = kv + (long)s * LATENT;
    float* out = kfull + (long)s * LATENT;
    __shared__ float red[256];
    float ss = 0.f;
    for (int i = tid; i < KV_LORA; i += 256) { float v = row[i]; ss += v * v; }
    red[tid] = ss; __syncthreads();
    for (int st = 128; st > 0; st >>= 1) {
        if (tid < st) red[tid] += red[tid + st];
        __syncthreads();
    }
    float r = rsqrtf(red[0] / (float)KV_LORA + 1e-6f);
    for (int i = tid; i < KV_LORA; i += 256) out[i] = row[i] * r * lnw[i];
    if (tid < ROPE_D) {
        int j = tid;
        float x = row[KV_LORA + j];
        float rot = (j < 32) ? -row[KV_LORA + j + 32] : row[KV_LORA + j - 32];
        out[KV_LORA + j] = x * cosb[s * ROPE_D + j] + rot * sinb[s * ROPE_D + j];
    }
}

// ---------------- rope(q_pe) -> split directly into qfull2 cols [512:576] ----------------
__global__ void rope_qpe2_k(const float* __restrict__ q,
                            const float* __restrict__ cosb, const float* __restrict__ sinb,
                            bf16* __restrict__ qfull2)
{
    int s = blockIdx.x;
    int h = blockIdx.y;
    int j = threadIdx.x;   // 0..63
    const float* x = q + (long)s * QBN + h * Q_HEAD + NOPE_D;
    float v = x[j];
    float rot = (j < 32) ? -x[j + 32] : x[j - 32];
    float val = v * cosb[s * ROPE_D + j] + rot * sinb[s * ROPE_D + j];
    bf16 hi, lo; split_bf16(val, hi, lo);
    bf16* row = qfull2 + ((long)h * S_LEN + s) * (3 * LATENT);
    row[KV_LORA + j] = hi;
    row[LATENT + KV_LORA + j] = hi;
    row[2 * LATENT + KV_LORA + j] = lo;
}

// ---------------- causal softmax fused with interleaved-triple bf16 output ----------------
// probs2[h][q][3k+0]=hi, [3k+1]=hi, [3k+2]=lo ; writes only k < round_up(q+1, 128)
__global__ void softmax_probs2_k(const float* __restrict__ scores, bf16* __restrict__ probs2)
{
    int q = blockIdx.x;
    int h = blockIdx.y;
    int tid = threadIdx.x;
    const float* row = scores + ((long)h * S_LEN + q) * S_LEN;
    bf16* orow = probs2 + ((long)h * S_LEN + q) * (3 * S_LEN);
    int n = q + 1;
    int imax = ((q >> 7) + 1) << 7;
    __shared__ float red[256];

    int i0 = tid * 4;
    bool act = i0 < imax;
    float a[4] = {0.f, 0.f, 0.f, 0.f};
    if (act) { float4 v = *(const float4*)(row + i0); a[0]=v.x; a[1]=v.y; a[2]=v.z; a[3]=v.w; }

    float mx = -3.4e38f;
#pragma unroll
    for (int j = 0; j < 4; j++)
        if (i0 + j < n) mx = fmaxf(mx, a[j]);
    red[tid] = mx; __syncthreads();
    for (int st = 128; st > 0; st >>= 1) {
        if (tid < st) red[tid] = fmaxf(red[tid], red[tid + st]);
        __syncthreads();
    }
    mx = red[0];
    __syncthreads();

    float sum = 0.f;
#pragma unroll
    for (int j = 0; j < 4; j++) {
        a[j] = (i0 + j < n) ? __expf(a[j] - mx) : 0.f;
        sum += a[j];
    }
    red[tid] = sum; __syncthreads();
    for (int st = 128; st > 0; st >>= 1) {
        if (tid < st) red[tid] += red[tid + st];
        __syncthreads();
    }
    float inv = 1.f / red[0];

    if (act) {
        __align__(8) bf16 buf[12];
#pragma unroll
        for (int j = 0; j < 4; j++) {
            float p = a[j] * inv;
            bf16 hi, lo; split_bf16(p, hi, lo);
            buf[3 * j + 0] = hi;
            buf[3 * j + 1] = hi;
            buf[3 * j + 2] = lo;
        }
        uint2* dst = (uint2*)(orow + 3 * i0);
        const uint2* sb = (const uint2*)buf;
        dst[0] = sb[0]; dst[1] = sb[1]; dst[2] = sb[2];
    }
}

// ---------------- host-side launchers ----------------
template<int EPI, int TRI, int KLIM>
static void gemm(const bf16* A, const bf16* B, void* C,
                 int M, int N, int K, int lda, int ldb, int ldc,
                 long sA, long sB, long sC, int batch, float alpha, int off2)
{
    dim3 grid;
    if (TRI) {
        int t = M / BM;
        grid = dim3(t * (t + 1) / 2, 1, batch);
    } else {
        grid = dim3((N + BN - 1) / BN, M / BM, batch);
    }
    gemm_t<EPI, TRI, KLIM><<<grid, 256>>>(A, B, C, M, N, K, lda, ldb, ldc, sA, sB, sC, alpha, off2);
}
static void convA(const float* src, bf16* dst, int M, int K, int lda, long ssrc, int batch)
{
    long total = (long)M * (K >> 2);
    int blocks = (int)((total + 255) / 256);
    if (blocks > 2048) blocks = 2048;
    convA4_k<<<dim3(blocks, 1, batch), 256>>>(src, dst, M, K, lda, ssrc);
}
static void convB(const float* src, bf16* dst, int K, int N, int ldb, long ssrc, int batch)
{
    long total = (long)K * (N >> 2);
    int blocks = (int)((total + 255) / 256);
    if (blocks > 2048) blocks = 2048;
    convB4_k<<<dim3(blocks, 1, batch), 256>>>(src, dst, K, N, ldb, ssrc);
}

extern "C" void kernel_launch(void* const* d_in, const int* in_sizes, int n_in,
                              void* d_out, int out_size)
{
    const float* h      = (const float*)d_in[0];
    const float* cosb   = (const float*)d_in[1];
    const float* sinb   = (const float*)d_in[2];
    const float* q_a_w  = (const float*)d_in[3];
    const float* q_a_ln = (const float*)d_in[4];
    const float* q_b_w  = (const float*)d_in[5];
    const float* kv_a_w = (const float*)d_in[6];
    const float* kv_ln  = (const float*)d_in[7];
    const float* kc_w   = (const float*)d_in[8];
    const float* vc_w   = (const float*)d_in[9];
    const float* o_w    = (const float*)d_in[10];
    float* out = (float*)d_out;

    bf16 *p_h2, *p_qaw2, *p_qa2, *p_qbw2, *p_qn2, *p_kc2, *p_kvaw2, *p_lat2, *p_kT2;
    bf16 *p_vc2, *p_qfull2, *p_veff2, *p_probs2, *p_bigo2, *p_ow2;
    float *p_qa, *p_q, *p_kv, *p_kfull, *p_scores;
    cudaGetSymbolAddress((void**)&p_h2,     g_h2);
    cudaGetSymbolAddress((void**)&p_qaw2,   g_qaw2);
    cudaGetSymbolAddress((void**)&p_qa2,    g_qa2);
    cudaGetSymbolAddress((void**)&p_qbw2,   g_qbw2);
    cudaGetSymbolAddress((void**)&p_qn2,    g_qn2);
    cudaGetSymbolAddress((void**)&p_kc2,    g_kc2);
    cudaGetSymbolAddress((void**)&p_kvaw2,  g_kvaw2);
    cudaGetSymbolAddress((void**)&p_lat2,   g_lat2);
    cudaGetSymbolAddress((void**)&p_kT2,    g_kT2);
    cudaGetSymbolAddress((void**)&p_vc2,    g_vc2);
    cudaGetSymbolAddress((void**)&p_qfull2, g_qfull2);
    cudaGetSymbolAddress((void**)&p_veff2,  g_veff2);
    cudaGetSymbolAddress((void**)&p_probs2, g_probs2);
    cudaGetSymbolAddress((void**)&p_bigo2,  g_bigo2);
    cudaGetSymbolAddress((void**)&p_ow2,    g_ow2);
    cudaGetSymbolAddress((void**)&p_qa,     g_qa);
    cudaGetSymbolAddress((void**)&p_q,      g_q);
    cudaGetSymbolAddress((void**)&p_kv,     g_kv);
    cudaGetSymbolAddress((void**)&p_kfull,  g_kfull);
    cudaGetSymbolAddress((void**)&p_scores, g_scores);

    double mscale = 0.1 * log(40.0) + 1.0;
    const float SCALE = (float)(pow((double)Q_HEAD, -0.5) * mscale * mscale);

    // ---- conversions (every call; no caching allowed) ----
    convA(h,      p_h2,    S_LEN, D_MODEL, D_MODEL, 0, 1);
    convB(q_a_w,  p_qaw2,  D_MODEL, Q_LORA, Q_LORA, 0, 1);
    convB(kv_a_w, p_kvaw2, D_MODEL, LATENT, LATENT, 0, 1);
    convB(q_b_w,  p_qbw2,  Q_LORA, QBN, QBN, 0, 1);
    convB(kc_w,   p_kc2,   NOPE_D, KV_LORA, KV_LORA, (long)NOPE_D * KV_LORA, H_HEADS);
    convB(vc_w,   p_vc2,   KV_LORA, VDIM, VDIM, (long)KV_LORA * VDIM, H_HEADS);
    convB(o_w,    p_ow2,   OUTW, D_MODEL, D_MODEL, 0, 1);

    // 1) qa = h @ q_a_w  (fp32 out)
    gemm<0,0,0>(p_h2, p_qaw2, p_qa, S_LEN, Q_LORA, 3 * D_MODEL,
                3 * D_MODEL, Q_LORA, Q_LORA, 0, 0, 0, 1, 1.f, 0);
    // 2) rmsnorm + split
    rmsnorm_rows_k<<<S_LEN, 256>>>(p_qa, q_a_ln, Q_LORA);
    convA(p_qa, p_qa2, S_LEN, Q_LORA, Q_LORA, 0, 1);
    // 3) q = qa_n @ q_b_w (fp32; consumed by per-head slicing + rope)
    gemm<0,0,0>(p_qa2, p_qbw2, p_q, S_LEN, QBN, 3 * Q_LORA,
                3 * Q_LORA, QBN, QBN, 0, 0, 0, 1, 1.f, 0);
    // 4) kv = h @ kv_a_w
    gemm<0,0,0>(p_h2, p_kvaw2, p_kv, S_LEN, LATENT, 3 * D_MODEL,
                3 * D_MODEL, LATENT, LATENT, 0, 0, 0, 1, 1.f, 0);
    // 5) k_full; split latent (A-style) + transposed k_full (B-style)
    build_kfull_k<<<S_LEN, 256>>>(p_kv, kv_ln, cosb, sinb, p_kfull);
    convA(p_kfull, p_lat2, S_LEN, KV_LORA, LATENT, 0, 1);
    {
        long total = (long)LATENT * S_LEN;
        int blocks = (int)((total + 255) / 256);
        convBt_k<<<blocks, 256>>>(p_kfull, p_kT2, LATENT, S_LEN, LATENT);
    }
    // 6) q_nope slices -> split; q_full[h][:, :512] via fused splitA epilogue
    convA(p_q, p_qn2, S_LEN, NOPE_D, QBN, (long)Q_HEAD, H_HEADS);
    gemm<1,0,0>(p_qn2, p_kc2, p_qfull2,
                S_LEN, KV_LORA, 3 * NOPE_D,
                3 * NOPE_D, KV_LORA, 3 * LATENT,
                (long)S_LEN * 3 * NOPE_D, (long)3 * NOPE_D * KV_LORA, (long)S_LEN * 3 * LATENT,
                H_HEADS, 1.f, LATENT);
    // 7) rope(q_pe) -> split directly into qfull2
    {
        dim3 grid(S_LEN, H_HEADS);
        rope_qpe2_k<<<grid, 64>>>(p_q, cosb, sinb, p_qfull2);
    }
    // 8) V_eff[h] = latent @ vc_w[h], fused splitB-interleave epilogue
    gemm<2,0,0>(p_lat2, p_vc2, p_veff2,
                S_LEN, VDIM, 3 * KV_LORA,
                3 * KV_LORA, VDIM, VDIM,
                0, (long)3 * KV_LORA * VDIM, (long)3 * S_LEN * VDIM,
                H_HEADS, 1.f, 0);
    // 9) scores (lower-triangle tiles only)
    gemm<0,1,0>(p_qfull2, p_kT2, p_scores,
                S_LEN, S_LEN, 3 * LATENT,
                3 * LATENT, S_LEN, S_LEN,
                (long)S_LEN * 3 * LATENT, 0, (long)S_LEN * S_LEN,
                H_HEADS, SCALE, 0);
    // 10) causal softmax -> interleaved split probs
    {
        dim3 grid(S_LEN, H_HEADS);
        softmax_probs2_k<<<grid, 256>>>(p_scores, p_probs2);
    }
    // 11) big_out = probs @ V_eff  (causal K-limit, fused splitA epilogue)
    gemm<1,0,1>(p_probs2, p_veff2, p_bigo2,
                S_LEN, VDIM, 3 * S_LEN,
                3 * S_LEN, VDIM, 3 * OUTW,
                (long)S_LEN * 3 * S_LEN, (long)3 * S_LEN * VDIM, (long)VDIM,
                H_HEADS, 1.f, OUTW);
    // 12) out = big_out @ o_w
    gemm<0,0,0>(p_bigo2, p_ow2, out, S_LEN, D_MODEL, 3 * OUTW,
                3 * OUTW, D_MODEL, D_MODEL, 0, 0, 0, 1, 1.f, 0);
}

// round 8
// speedup vs baseline: 3.0082x; 1.0395x over previous
#include <cuda_runtime.h>
#include <cuda_bf16.h>
#include <math.h>
#include <stdint.h>

// ---------------- problem constants ----------------
#define S_LEN   1024
#define D_MODEL 5120
#define H_HEADS 128
#define Q_LORA  1536
#define KV_LORA 512
#define ROPE_D  64
#define NOPE_D  128
#define VDIM    128
#define Q_HEAD  192
#define LATENT  576
#define QBN     24576
#define OUTW    16384

typedef __nv_bfloat16 bf16;

// ---------------- scratch (device globals; no allocation) ----------------
__device__ __align__(16) bf16 g_h2    [(size_t)S_LEN * 3 * D_MODEL];
__device__ __align__(16) bf16 g_qaw2  [(size_t)3 * D_MODEL * Q_LORA];
__device__ __align__(16) bf16 g_qa2   [(size_t)S_LEN * 3 * Q_LORA];
__device__ __align__(16) bf16 g_qbw2  [(size_t)3 * Q_LORA * QBN];
__device__ __align__(16) bf16 g_qn2   [(size_t)H_HEADS * S_LEN * 3 * NOPE_D];
__device__ __align__(16) bf16 g_kc2   [(size_t)H_HEADS * 3 * NOPE_D * KV_LORA];
__device__ __align__(16) bf16 g_kvaw2 [(size_t)3 * D_MODEL * LATENT];
__device__ __align__(16) bf16 g_lat2  [(size_t)S_LEN * 3 * KV_LORA];
__device__ __align__(16) bf16 g_kT2   [(size_t)3 * LATENT * S_LEN];
__device__ __align__(16) bf16 g_vc2   [(size_t)H_HEADS * 3 * KV_LORA * VDIM];
__device__ __align__(16) bf16 g_qfull2[(size_t)H_HEADS * S_LEN * 3 * LATENT];
__device__ __align__(16) bf16 g_veff2 [(size_t)H_HEADS * 3 * S_LEN * VDIM];
__device__ __align__(16) bf16 g_probs2[(size_t)H_HEADS * S_LEN * 3 * S_LEN];
__device__ __align__(16) bf16 g_bigo2 [(size_t)S_LEN * 3 * OUTW];
__device__ __align__(16) bf16 g_ow2   [(size_t)3 * OUTW * D_MODEL];
// fp32 intermediates
__device__ __align__(16) float g_qa   [(size_t)S_LEN * Q_LORA];
__device__ __align__(16) float g_q    [(size_t)S_LEN * QBN];
__device__ __align__(16) float g_kv   [(size_t)S_LEN * LATENT];
__device__ __align__(16) float g_kfull[(size_t)S_LEN * LATENT];
__device__ __align__(16) float g_scores[(size_t)H_HEADS * S_LEN * S_LEN];

// ---------------- PTX helpers ----------------
__device__ __forceinline__ void cp_async16(uint32_t dst, const void* src, bool pred) {
    int sz = pred ? 16 : 0;
    asm volatile("cp.async.cg.shared.global [%0], [%1], 16, %2;\n"
                 :: "r"(dst), "l"(src), "r"(sz));
}
__device__ __forceinline__ void cp_commit() {
    asm volatile("cp.async.commit_group;\n" ::: "memory");
}
__device__ __forceinline__ void ldsm_x4(uint32_t* r, uint32_t addr) {
    asm volatile("ldmatrix.sync.aligned.m8n8.x4.shared.b16 {%0,%1,%2,%3}, [%4];\n"
                 : "=r"(r[0]), "=r"(r[1]), "=r"(r[2]), "=r"(r[3]) : "r"(addr));
}
__device__ __forceinline__ void ldsm_x4_t(uint32_t* r, uint32_t addr) {
    asm volatile("ldmatrix.sync.aligned.m8n8.x4.trans.shared.b16 {%0,%1,%2,%3}, [%4];\n"
                 : "=r"(r[0]), "=r"(r[1]), "=r"(r[2]), "=r"(r[3]) : "r"(addr));
}
__device__ __forceinline__ void mma_bf16(float* d, const uint32_t* a, const uint32_t* b) {
    asm volatile("mma.sync.aligned.m16n8k16.row.col.f32.bf16.bf16.f32 "
                 "{%0,%1,%2,%3},{%4,%5,%6,%7},{%8,%9},{%0,%1,%2,%3};\n"
                 : "+f"(d[0]), "+f"(d[1]), "+f"(d[2]), "+f"(d[3])
                 : "r"(a[0]), "r"(a[1]), "r"(a[2]), "r"(a[3]), "r"(b[0]), "r"(b[1]));
}

__device__ __forceinline__ void split_bf16(float x, bf16& hi, bf16& lo) {
    hi = __float2bfloat16(x);
    lo = __float2bfloat16(x - __bfloat162float(hi));
}

// ---------------- templated bf16 tensor-core GEMM: 128x128x64, 3-stage ----------------
// EPI: 0 = fp32 C;  1 = splitA [hi|hi|lo] (off2 = copy distance);
//      2 = splitB interleaved rows (3m:hi, 3m+1:lo, 3m+2:hi)
// TRI: lower-triangular tile launch; KLIM: Keff = min(K, 3*(m0+BM))
#define BM 128
#define BN 128
#define BK 64
#define ASTR (BK + 8)    // 72
#define BSTR (BN + 8)    // 136
#define NSTG 3
#define A_STG (BM * ASTR)            // elems per A stage
#define B_STG (BK * BSTR)            // elems per B stage
#define SMEM_ELEMS (NSTG * (A_STG + B_STG))
#define SMEM_BYTES (SMEM_ELEMS * 2)

template<int EPI, int TRI, int KLIM>
__global__ void __launch_bounds__(256, 2) gemm_t(
    const bf16* __restrict__ A, const bf16* __restrict__ B, void* __restrict__ Cv,
    int M, int N, int K, int lda, int ldb, int ldc,
    long sA, long sB, long sC, float alpha, int off2)
{
    extern __shared__ bf16 smem[];
    bf16 (*As)[BM][ASTR] = (bf16(*)[BM][ASTR])smem;
    bf16 (*Bs)[BK][BSTR] = (bf16(*)[BK][BSTR])(smem + NSTG * A_STG);

    int tm, tn;
    if (TRI) {
        int x = blockIdx.x;
        int r = (int)((-1.f + sqrtf(1.f + 8.f * (float)x)) * 0.5f);
        while ((r + 1) * (r + 2) / 2 <= x) ++r;
        while (r * (r + 1) / 2 > x) --r;
        tm = r; tn = x - r * (r + 1) / 2;
    } else { tn = blockIdx.x; tm = blockIdx.y; }

    const int m0 = tm * BM;
    const int n0 = tn * BN;
    A += (long)blockIdx.z * sA;
    B += (long)blockIdx.z * sB;

    int Keff = K;
    if (KLIM) { int lim = 3 * (m0 + BM); Keff = (lim < K) ? lim : K; }

    const int tid  = threadIdx.x;
    const int lane = tid & 31;
    const int warp = tid >> 5;
    const int wm   = warp >> 1;
    const int wn   = warp & 1;

    float acc[2][8][4];
#pragma unroll
    for (int a = 0; a < 2; a++)
#pragma unroll
        for (int b = 0; b < 8; b++)
#pragma unroll
            for (int c = 0; c < 4; c++) acc[a][b][c] = 0.f;

    const int ktiles = Keff / BK;

    auto load_tiles = [&](int buf, int kt) {
#pragma unroll
        for (int i = 0; i < 4; i++) {           // A: 1024 16B-chunks
            int seg = tid + 256 * i;
            int r = seg >> 3, c = (seg & 7) * 8;
            uint32_t dst = (uint32_t)__cvta_generic_to_shared(&As[buf][r][c]);
            cp_async16(dst, A + (long)(m0 + r) * lda + kt + c, true);
        }
#pragma unroll
        for (int i = 0; i < 4; i++) {           // B: 1024 16B-chunks
            int seg = tid + 256 * i;
            int r = seg >> 4, c = (seg & 15) * 8;
            uint32_t dst = (uint32_t)__cvta_generic_to_shared(&Bs[buf][r][c]);
            bool ok = (n0 + c) < N;
            const bf16* src = ok ? (B + (long)(kt + r) * ldb + n0 + c) : B;
            cp_async16(dst, src, ok);
        }
        cp_commit();
    };

    load_tiles(0, 0);
    if (ktiles > 1) load_tiles(1, BK);

    for (int t = 0; t < ktiles; t++) {
        const int buf = t % NSTG;
        if (t + 2 < ktiles) {
            load_tiles((t + 2) % NSTG, (t + 2) * BK);
            asm volatile("cp.async.wait_group 2;" ::: "memory");
        } else if (t + 1 < ktiles) {
            asm volatile("cp.async.wait_group 1;" ::: "memory");
        } else {
            asm volatile("cp.async.wait_group 0;" ::: "memory");
        }
        __syncthreads();

#pragma unroll
        for (int kk = 0; kk < 4; kk++) {
            uint32_t af[2][4];
#pragma unroll
            for (int mt = 0; mt < 2; mt++) {
                uint32_t addr = (uint32_t)__cvta_generic_to_shared(
                    &As[buf][wm * 32 + mt * 16 + (lane & 15)][kk * 16 + (lane >> 4) * 8]);
                ldsm_x4(af[mt], addr);
            }
            uint32_t bfr[4][4];
#pragma unroll
            for (int np = 0; np < 4; np++) {
                uint32_t addr = (uint32_t)__cvta_generic_to_shared(
                    &Bs[buf][kk * 16 + (lane & 15)][wn * 64 + np * 16 + (lane >> 4) * 8]);
                ldsm_x4_t(bfr[np], addr);
            }
#pragma unroll
            for (int mt = 0; mt < 2; mt++)
#pragma unroll
                for (int nt = 0; nt < 8; nt++)
                    mma_bf16(acc[mt][nt], af[mt], &bfr[nt >> 1][(nt & 1) * 2]);
        }
        __syncthreads();
    }

    // ---- epilogue ----
    const int r  = lane >> 2;
    const int c2 = (lane & 3) * 2;

    auto emit = [&](int m, int n, float v0, float v1) {
        v0 *= alpha; v1 *= alpha;
        if (EPI == 0) {
            float* C = (float*)Cv + (long)blockIdx.z * sC;
            C[(long)m * ldc + n]     = v0;
            C[(long)m * ldc + n + 1] = v1;
        } else if (EPI == 1) {
            bf16* C = (bf16*)Cv + (long)blockIdx.z * sC;
            bf16 h0, l0, h1, l1;
            split_bf16(v0, h0, l0); split_bf16(v1, h1, l1);
            __nv_bfloat162 hi2 = __nv_bfloat162(h0, h1);
            __nv_bfloat162 lo2 = __nv_bfloat162(l0, l1);
            long base = (long)m * ldc + n;
            *(__nv_bfloat162*)&C[base] = hi2;
            *(__nv_bfloat162*)&C[base + off2] = hi2;
            *(__nv_bfloat162*)&C[base + 2 * off2] = lo2;
        } else {
            bf16* C = (bf16*)Cv + (long)blockIdx.z * sC;
            bf16 h0, l0, h1, l1;
            split_bf16(v0, h0, l0); split_bf16(v1, h1, l1);
            __nv_bfloat162 hi2 = __nv_bfloat162(h0, h1);
            __nv_bfloat162 lo2 = __nv_bfloat162(l0, l1);
            *(__nv_bfloat162*)&C[(long)(3 * m)     * ldc + n] = hi2;
            *(__nv_bfloat162*)&C[(long)(3 * m + 1) * ldc + n] = lo2;
            *(__nv_bfloat162*)&C[(long)(3 * m + 2) * ldc + n] = hi2;
        }
    };

#pragma unroll
    for (int mt = 0; mt < 2; mt++) {
#pragma unroll
        for (int nt = 0; nt < 8; nt++) {
            int m = m0 + wm * 32 + mt * 16 + r;
            int n = n0 + wn * 64 + nt * 8 + c2;
            if (n < N) {
                emit(m,     n, acc[mt][nt][0], acc[mt][nt][1]);
                emit(m + 8, n, acc[mt][nt][2], acc[mt][nt][3]);
            }
        }
    }
}

// ---------------- vectorized converters ----------------
union BV4 { bf16 b[4]; uint2 u; };

__global__ void convA4_k(const float* __restrict__ src, bf16* __restrict__ dst,
                         int M, int K, int lda, long ssrc)
{
    src += (long)blockIdx.z * ssrc;
    dst += (long)blockIdx.z * M * 3 * K;
    int K4 = K >> 2;
    long total = (long)M * K4;
    for (long idx = (long)blockIdx.x * blockDim.x + threadIdx.x; idx < total;
         idx += (long)gridDim.x * blockDim.x) {
        int m = (int)(idx / K4), k = (int)(idx % K4) * 4;
        float4 x = *(const float4*)(src + (long)m * lda + k);
        BV4 hv, lv;
        split_bf16(x.x, hv.b[0], lv.b[0]);
        split_bf16(x.y, hv.b[1], lv.b[1]);
        split_bf16(x.z, hv.b[2], lv.b[2]);
        split_bf16(x.w, hv.b[3], lv.b[3]);
        bf16* row = dst + (long)m * 3 * K;
        *(uint2*)&row[k]         = hv.u;
        *(uint2*)&row[K + k]     = hv.u;
        *(uint2*)&row[2 * K + k] = lv.u;
    }
}

__global__ void convB4_k(const float* __restrict__ src, bf16* __restrict__ dst,
                         int K, int N, int ldb, long ssrc)
{
    src += (long)blockIdx.z * ssrc;
    dst += (long)blockIdx.z * 3 * K * N;
    int N4 = N >> 2;
    long total = (long)K * N4;
    for (long idx = (long)blockIdx.x * blockDim.x + threadIdx.x; idx < total;
         idx += (long)gridDim.x * blockDim.x) {
        int k = (int)(idx / N4), n = (int)(idx % N4) * 4;
        float4 x = *(const float4*)(src + (long)k * ldb + n);
        BV4 hv, lv;
        split_bf16(x.x, hv.b[0], lv.b[0]);
        split_bf16(x.y, hv.b[1], lv.b[1]);
        split_bf16(x.z, hv.b[2], lv.b[2]);
        split_bf16(x.w, hv.b[3], lv.b[3]);
        *(uint2*)&dst[(long)k * N + n]           = hv.u;
        *(uint2*)&dst[((long)K + k) * N + n]     = lv.u;
        *(uint2*)&dst[((long)2 * K + k) * N + n] = hv.u;
    }
}

__global__ void convBt_k(const float* __restrict__ src, bf16* __restrict__ dst,
                         int K, int N, int lds)
{
    long total = (long)K * N;
    for (long idx = (long)blockIdx.x * blockDim.x + threadIdx.x; idx < total;
         idx += (long)gridDim.x * blockDim.x) {
        int k = (int)(idx / N), n = (int)(idx % N);
        float x = src[(long)n * lds + k];
        bf16 hi, lo; split_bf16(x, hi, lo);
        dst[(long)k * N + n] = hi;
        dst[((long)K + k) * N + n] = lo;
        dst[((long)2 * K + k) * N + n] = hi;
    }
}

// ---------------- elementwise kernels ----------------
__global__ void rmsnorm_rows_k(float* x, const float* __restrict__ w, int W)
{
    int row = blockIdx.x;
    float* p = x + (long)row * W;
    __shared__ float red[256];
    int tid = threadIdx.x;
    float ss = 0.f;
    for (int i = tid; i < W; i += 256) { float v = p[i]; ss += v * v; }
    red[tid] = ss; __syncthreads();
    for (int st = 128; st > 0; st >>= 1) {
        if (tid < st) red[tid] += red[tid + st];
        __syncthreads();
    }
    float r = rsqrtf(red[0] / (float)W + 1e-6f);
    for (int i = tid; i < W; i += 256) p[i] = p[i] * r * w[i];
}

__global__ void build_kfull_k(const float* __restrict__ kv, const float* __restrict__ lnw,
                              const float* __restrict__ cosb, const float* __restrict__ sinb,
                              float* __restrict__ kfull)
{
    int s = blockIdx.x;
    int tid = threadIdx.x;
    const float* row = kv + (long)s * LATENT;
    float* out = kfull + (long)s * LATENT;
    __shared__ float red[256];
    float ss = 0.f;
    for (int i = tid; i < KV_LORA; i += 256) { float v = row[i]; ss += v * v; }
    red[tid] = ss; __syncthreads();
    for (int st = 128; st > 0; st >>= 1) {
        if (tid < st) red[tid] += red[tid + st];
        __syncthreads();
    }
    float r = rsqrtf(red[0] / (float)KV_LORA + 1e-6f);
    for (int i = tid; i < KV_LORA; i += 256) out[i] = row[i] * r * lnw[i];
    if (tid < ROPE_D) {
        int j = tid;
        float x = row[KV_LORA + j];
        float rot = (j < 32) ? -row[KV_LORA + j + 32] : row[KV_LORA + j - 32];
        out[KV_LORA + j] = x * cosb[s * ROPE_D + j] + rot * sinb[s * ROPE_D + j];
    }
}

__global__ void rope_qpe2_k(const float* __restrict__ q,
                            const float* __restrict__ cosb, const float* __restrict__ sinb,
                            bf16* __restrict__ qfull2)
{
    int s = blockIdx.x;
    int h = blockIdx.y;
    int j = threadIdx.x;
    const float* x = q + (long)s * QBN + h * Q_HEAD + NOPE_D;
    float v = x[j];
    float rot = (j < 32) ? -x[j + 32] : x[j - 32];
    float val = v * cosb[s * ROPE_D + j] + rot * sinb[s * ROPE_D + j];
    bf16 hi, lo; split_bf16(val, hi, lo);
    bf16* row = qfull2 + ((long)h * S_LEN + s) * (3 * LATENT);
    row[KV_LORA + j] = hi;
    row[LATENT + KV_LORA + j] = hi;
    row[2 * LATENT + KV_LORA + j] = lo;
}

__global__ void softmax_probs2_k(const float* __restrict__ scores, bf16* __restrict__ probs2)
{
    int q = blockIdx.x;
    int h = blockIdx.y;
    int tid = threadIdx.x;
    const float* row = scores + ((long)h * S_LEN + q) * S_LEN;
    bf16* orow = probs2 + ((long)h * S_LEN + q) * (3 * S_LEN);
    int n = q + 1;
    int imax = ((q >> 7) + 1) << 7;
    __shared__ float red[256];

    int i0 = tid * 4;
    bool act = i0 < imax;
    float a[4] = {0.f, 0.f, 0.f, 0.f};
    if (act) { float4 v = *(const float4*)(row + i0); a[0]=v.x; a[1]=v.y; a[2]=v.z; a[3]=v.w; }

    float mx = -3.4e38f;
#pragma unroll
    for (int j = 0; j < 4; j++)
        if (i0 + j < n) mx = fmaxf(mx, a[j]);
    red[tid] = mx; __syncthreads();
    for (int st = 128; st > 0; st >>= 1) {
        if (tid < st) red[tid] = fmaxf(red[tid], red[tid + st]);
        __syncthreads();
    }
    mx = red[0];
    __syncthreads();

    float sum = 0.f;
#pragma unroll
    for (int j = 0; j < 4; j++) {
        a[j] = (i0 + j < n) ? __expf(a[j] - mx) : 0.f;
        sum += a[j];
    }
    red[tid] = sum; __syncthreads();
    for (int st = 128; st > 0; st >>= 1) {
        if (tid < st) red[tid] += red[tid + st];
        __syncthreads();
    }
    float inv = 1.f / red[0];

    if (act) {
        __align__(8) bf16 buf[12];
#pragma unroll
        for (int j = 0; j < 4; j++) {
            float p = a[j] * inv;
            bf16 hi, lo; split_bf16(p, hi, lo);
            buf[3 * j + 0] = hi;
            buf[3 * j + 1] = hi;
            buf[3 * j + 2] = lo;
        }
        uint2* dst = (uint2*)(orow + 3 * i0);
        const uint2* sb = (const uint2*)buf;
        dst[0] = sb[0]; dst[1] = sb[1]; dst[2] = sb[2];
    }
}

// ---------------- host-side launchers ----------------
template<int EPI, int TRI, int KLIM>
static void gemm(const bf16* A, const bf16* B, void* C,
                 int M, int N, int K, int lda, int ldb, int ldc,
                 long sA, long sB, long sC, int batch, float alpha, int off2)
{
    cudaFuncSetAttribute(gemm_t<EPI, TRI, KLIM>,
                         cudaFuncAttributeMaxDynamicSharedMemorySize, SMEM_BYTES);
    dim3 grid;
    if (TRI) {
        int t = M / BM;
        grid = dim3(t * (t + 1) / 2, 1, batch);
    } else {
        grid = dim3((N + BN - 1) / BN, M / BM, batch);
    }
    gemm_t<EPI, TRI, KLIM><<<grid, 256, SMEM_BYTES>>>(A, B, C, M, N, K, lda, ldb, ldc,
                                                      sA, sB, sC, alpha, off2);
}
static void convA(const float* src, bf16* dst, int M, int K, int lda, long ssrc, int batch)
{
    long total = (long)M * (K >> 2);
    int blocks = (int)((total + 255) / 256);
    if (blocks > 2048) blocks = 2048;
    convA4_k<<<dim3(blocks, 1, batch), 256>>>(src, dst, M, K, lda, ssrc);
}
static void convB(const float* src, bf16* dst, int K, int N, int ldb, long ssrc, int batch)
{
    long total = (long)K * (N >> 2);
    int blocks = (int)((total + 255) / 256);
    if (blocks > 2048) blocks = 2048;
    convB4_k<<<dim3(blocks, 1, batch), 256>>>(src, dst, K, N, ldb, ssrc);
}

extern "C" void kernel_launch(void* const* d_in, const int* in_sizes, int n_in,
                              void* d_out, int out_size)
{
    const float* h      = (const float*)d_in[0];
    const float* cosb   = (const float*)d_in[1];
    const float* sinb   = (const float*)d_in[2];
    const float* q_a_w  = (const float*)d_in[3];
    const float* q_a_ln = (const float*)d_in[4];
    const float* q_b_w  = (const float*)d_in[5];
    const float* kv_a_w = (const float*)d_in[6];
    const float* kv_ln  = (const float*)d_in[7];
    const float* kc_w   = (const float*)d_in[8];
    const float* vc_w   = (const float*)d_in[9];
    const float* o_w    = (const float*)d_in[10];
    float* out = (float*)d_out;

    bf16 *p_h2, *p_qaw2, *p_qa2, *p_qbw2, *p_qn2, *p_kc2, *p_kvaw2, *p_lat2, *p_kT2;
    bf16 *p_vc2, *p_qfull2, *p_veff2, *p_probs2, *p_bigo2, *p_ow2;
    float *p_qa, *p_q, *p_kv, *p_kfull, *p_scores;
    cudaGetSymbolAddress((void**)&p_h2,     g_h2);
    cudaGetSymbolAddress((void**)&p_qaw2,   g_qaw2);
    cudaGetSymbolAddress((void**)&p_qa2,    g_qa2);
    cudaGetSymbolAddress((void**)&p_qbw2,   g_qbw2);
    cudaGetSymbolAddress((void**)&p_qn2,    g_qn2);
    cudaGetSymbolAddress((void**)&p_kc2,    g_kc2);
    cudaGetSymbolAddress((void**)&p_kvaw2,  g_kvaw2);
    cudaGetSymbolAddress((void**)&p_lat2,   g_lat2);
    cudaGetSymbolAddress((void**)&p_kT2,    g_kT2);
    cudaGetSymbolAddress((void**)&p_vc2,    g_vc2);
    cudaGetSymbolAddress((void**)&p_qfull2, g_qfull2);
    cudaGetSymbolAddress((void**)&p_veff2,  g_veff2);
    cudaGetSymbolAddress((void**)&p_probs2, g_probs2);
    cudaGetSymbolAddress((void**)&p_bigo2,  g_bigo2);
    cudaGetSymbolAddress((void**)&p_ow2,    g_ow2);
    cudaGetSymbolAddress((void**)&p_qa,     g_qa);
    cudaGetSymbolAddress((void**)&p_q,      g_q);
    cudaGetSymbolAddress((void**)&p_kv,     g_kv);
    cudaGetSymbolAddress((void**)&p_kfull,  g_kfull);
    cudaGetSymbolAddress((void**)&p_scores, g_scores);

    double mscale = 0.1 * log(40.0) + 1.0;
    const float SCALE = (float)(pow((double)Q_HEAD, -0.5) * mscale * mscale);

    // ---- conversions ----
    convA(h,      p_h2,    S_LEN, D_MODEL, D_MODEL, 0, 1);
    convB(q_a_w,  p_qaw2,  D_MODEL, Q_LORA, Q_LORA, 0, 1);
    convB(kv_a_w, p_kvaw2, D_MODEL, LATENT, LATENT, 0, 1);
    convB(q_b_w,  p_qbw2,  Q_LORA, QBN, QBN, 0, 1);
    convB(kc_w,   p_kc2,   NOPE_D, KV_LORA, KV_LORA, (long)NOPE_D * KV_LORA, H_HEADS);
    convB(vc_w,   p_vc2,   KV_LORA, VDIM, VDIM, (long)KV_LORA * VDIM, H_HEADS);
    convB(o_w,    p_ow2,   OUTW, D_MODEL, D_MODEL, 0, 1);

    // 1) qa = h @ q_a_w
    gemm<0,0,0>(p_h2, p_qaw2, p_qa, S_LEN, Q_LORA, 3 * D_MODEL,
                3 * D_MODEL, Q_LORA, Q_LORA, 0, 0, 0, 1, 1.f, 0);
    // 2) rmsnorm + split
    rmsnorm_rows_k<<<S_LEN, 256>>>(p_qa, q_a_ln, Q_LORA);
    convA(p_qa, p_qa2, S_LEN, Q_LORA, Q_LORA, 0, 1);
    // 3) q = qa_n @ q_b_w
    gemm<0,0,0>(p_qa2, p_qbw2, p_q, S_LEN, QBN, 3 * Q_LORA,
                3 * Q_LORA, QBN, QBN, 0, 0, 0, 1, 1.f, 0);
    // 4) kv = h @ kv_a_w
    gemm<0,0,0>(p_h2, p_kvaw2, p_kv, S_LEN, LATENT, 3 * D_MODEL,
                3 * D_MODEL, LATENT, LATENT, 0, 0, 0, 1, 1.f, 0);
    // 5) k_full; split latent (A-style) + transposed k_full (B-style)
    build_kfull_k<<<S_LEN, 256>>>(p_kv, kv_ln, cosb, sinb, p_kfull);
    convA(p_kfull, p_lat2, S_LEN, KV_LORA, LATENT, 0, 1);
    {
        long total = (long)LATENT * S_LEN;
        int blocks = (int)((total + 255) / 256);
        convBt_k<<<blocks, 256>>>(p_kfull, p_kT2, LATENT, S_LEN, LATENT);
    }
    // 6) q_nope slices -> split; q_full[:, :512] fused splitA epilogue
    convA(p_q, p_qn2, S_LEN, NOPE_D, QBN, (long)Q_HEAD, H_HEADS);
    gemm<1,0,0>(p_qn2, p_kc2, p_qfull2,
                S_LEN, KV_LORA, 3 * NOPE_D,
                3 * NOPE_D, KV_LORA, 3 * LATENT,
                (long)S_LEN * 3 * NOPE_D, (long)3 * NOPE_D * KV_LORA,
                (long)S_LEN * 3 * LATENT, H_HEADS, 1.f, LATENT);
    // 7) rope(q_pe)
    {
        dim3 grid(S_LEN, H_HEADS);
        rope_qpe2_k<<<grid, 64>>>(p_q, cosb, sinb, p_qfull2);
    }
    // 8) V_eff[h] = latent @ vc_w[h], fused splitB-interleave epilogue
    gemm<2,0,0>(p_lat2, p_vc2, p_veff2,
                S_LEN, VDIM, 3 * KV_LORA,
                3 * KV_LORA, VDIM, VDIM,
                0, (long)3 * KV_LORA * VDIM, (long)3 * S_LEN * VDIM,
                H_HEADS, 1.f, 0);
    // 9) scores (lower-triangle tiles only)
    gemm<0,1,0>(p_qfull2, p_kT2, p_scores,
                S_LEN, S_LEN, 3 * LATENT,
                3 * LATENT, S_LEN, S_LEN,
                (long)S_LEN * 3 * LATENT, 0, (long)S_LEN * S_LEN,
                H_HEADS, SCALE, 0);
    // 10) causal softmax -> interleaved split probs
    {
        dim3 grid(S_LEN, H_HEADS);
        softmax_probs2_k<<<grid, 256>>>(p_scores, p_probs2);
    }
    // 11) big_out = probs @ V_eff (causal K-limit, fused splitA epilogue)
    gemm<1,0,1>(p_probs2, p_veff2, p_bigo2,
                S_LEN, VDIM, 3 * S_LEN,
                3 * S_LEN, VDIM, 3 * OUTW,
                (long)S_LEN * 3 * S_LEN, (long)3 * S_LEN * VDIM, (long)VDIM,
                H_HEADS, 1.f, OUTW);
    // 12) out = big_out @ o_w
    gemm<0,0,0>(p_bigo2, p_ow2, out, S_LEN, D_MODEL, 3 * OUTW,
                3 * OUTW, D_MODEL, D_MODEL, 0, 0, 0, 1, 1.f, 0);
}